// round 12
// baseline (speedup 1.0000x reference)
#include <cuda_runtime.h>
#include <cuda.h>
#include <cuda_fp16.h>
#include <stdint.h>
#include <math.h>

#define SEQ    1024
#define BSZ    4
#define DMODEL 1024
#define NHEAD  16
#define HDIM   64
#define DFF_   4096
#define MROWS  (SEQ*BSZ)

// ---------------- scratch (device globals; no allocation allowed) ------------
__device__ __align__(1024) __half g_qkvh[MROWS*3072];
__device__ __align__(1024) __half g_qvh [MROWS*2048];
__device__ __align__(1024) __half g_kh  [MROWS*DMODEL];
__device__ __align__(1024) __half g_attnh[MROWS*DMODEL];
__device__ __align__(1024) __half g_ffnh[MROWS*DFF_];
__device__ __align__(1024) __half g_rinh[MROWS*DMODEL];
__device__ __align__(1024) __half g_renh[MROWS*DMODEL];
__device__ __align__(1024) __half g_x1h [MROWS*DMODEL];
__device__ __align__(1024) __half g_x2h [MROWS*DMODEL];
__device__ __align__(1024) __half g_wh  [16*1024*1024];
__device__ __align__(1024) float  g_tmp [MROWS*DMODEL];
__device__ __align__(1024) float  g_x1  [MROWS*DMODEL];
__device__ __align__(1024) float  g_x2  [MROWS*DMODEL];
__device__ __align__(1024) float  g_bias[8192];

// ---------------- helpers -------------------------------------------------
__device__ __forceinline__ uint32_t smem_u32(const void* p) {
    uint32_t a;
    asm("{ .reg .u64 t; cvta.to.shared.u64 t, %1; cvt.u32.u64 %0, t; }" : "=r"(a) : "l"(p));
    return a;
}
__device__ __forceinline__ void cp16(uint32_t dst, const void* src) {
    asm volatile("cp.async.cg.shared.global [%0], [%1], 16;" :: "r"(dst), "l"(src));
}
#define CP_COMMIT() asm volatile("cp.async.commit_group;" ::: "memory")
#define CP_WAIT(N)  asm volatile("cp.async.wait_group %0;" :: "n"(N) : "memory")

#define LDSM4(r0, r1, r2, r3, addr) \
    asm volatile("ldmatrix.sync.aligned.m8n8.x4.shared.b16 {%0,%1,%2,%3}, [%4];" \
        : "=r"(r0), "=r"(r1), "=r"(r2), "=r"(r3) : "r"(addr))
#define LDSM4T(r0, r1, r2, r3, addr) \
    asm volatile("ldmatrix.sync.aligned.m8n8.x4.trans.shared.b16 {%0,%1,%2,%3}, [%4];" \
        : "=r"(r0), "=r"(r1), "=r"(r2), "=r"(r3) : "r"(addr))

__device__ __forceinline__ void mma_f16(float c[4], const uint32_t a[4], const uint32_t b[2]) {
    asm volatile(
        "mma.sync.aligned.m16n8k16.row.col.f32.f16.f16.f32 "
        "{%0,%1,%2,%3}, {%4,%5,%6,%7}, {%8,%9}, {%0,%1,%2,%3};"
        : "+f"(c[0]), "+f"(c[1]), "+f"(c[2]), "+f"(c[3])
        : "r"(a[0]), "r"(a[1]), "r"(a[2]), "r"(a[3]), "r"(b[0]), "r"(b[1]));
}

// ---------------- fp16 mma GEMM: C[M,N] = A[M,K] @ W[N,K]^T + bias -----------
// CTA 128x128, 256 threads / 8 warps (4M x 2N), warp tile 32x64, BK=64,
// 3-stage cp.async (2 in flight), XOR-swizzled smem, 2 CTAs/SM.
static constexpr int STAGE_B = 32768;                 // 16KB A + 16KB B
static constexpr int GEMM_DSMEM = 3 * STAGE_B;        // 98304

template <int RELU, int OUTH>
__global__ __launch_bounds__(256, 2)
void gemm_h_kernel(const __half* __restrict__ A, const __half* __restrict__ W,
                   const float* __restrict__ bias, void* __restrict__ Cv,
                   int Nn, int Kn) {
    extern __shared__ char dsmc[];
    const int tid = threadIdx.x, lane = tid & 31, wid = tid >> 5;
    const int g = lane >> 2, t = lane & 3;
    const int bm = blockIdx.y * 128, bn = blockIdx.x * 128;
    const int wm = (wid & 3) * 32, wn = (wid >> 2) * 64;

    float acc[2][8][4];
    #pragma unroll
    for (int mt = 0; mt < 2; mt++)
        #pragma unroll
        for (int nt = 0; nt < 8; nt++)
            #pragma unroll
            for (int i = 0; i < 4; i++) acc[mt][nt][i] = 0.0f;

    const int NIT = Kn / 64;
    const uint32_t sb = smem_u32(dsmc);

    const int lr = tid >> 3, lc = tid & 7;
    auto load_stage = [&](int st, int kk) {
        uint32_t abase = sb + st * STAGE_B;
        uint32_t bbase = abase + 16384;
        #pragma unroll
        for (int p = 0; p < 4; p++) {
            int r = lr + p * 32;
            cp16(abase + r * 128 + ((lc ^ (r & 7)) << 4),
                 A + (size_t)(bm + r) * Kn + kk + lc * 8);
        }
        #pragma unroll
        for (int p = 0; p < 4; p++) {
            int r = lr + p * 32;
            cp16(bbase + r * 128 + ((lc ^ (r & 7)) << 4),
                 W + (size_t)(bn + r) * Kn + kk + lc * 8);
        }
        CP_COMMIT();
    };

    load_stage(0, 0);
    load_stage(1, 64);

    const int arow = wm + (lane & 15);
    const int axor = lane & 7;
    const int ach  = (lane >> 4) & 1;
    const int brow = wn + (lane & 7) + ((lane >> 4) & 1) * 8;
    const int bxor = lane & 7;
    const int bch  = (lane >> 3) & 1;

    for (int it = 0; it < NIT; it++) {
        const int cur = it % 3;
        CP_WAIT(1);
        __syncthreads();
        if (it + 2 < NIT) load_stage((it + 2) % 3, (it + 2) * 64);
        else              CP_COMMIT();

        const uint32_t ab = sb + cur * STAGE_B;
        const uint32_t bb = ab + 16384;

        #pragma unroll
        for (int ks = 0; ks < 4; ks++) {
            uint32_t a[2][4], b[8][2];
            const int cA = (2 * ks + ach) ^ axor;
            const int cB = (2 * ks + bch) ^ bxor;
            #pragma unroll
            for (int mt = 0; mt < 2; mt++)
                LDSM4(a[mt][0], a[mt][1], a[mt][2], a[mt][3],
                      ab + (arow + mt * 16) * 128 + (cA << 4));
            #pragma unroll
            for (int p = 0; p < 4; p++)
                LDSM4(b[2*p][0], b[2*p][1], b[2*p+1][0], b[2*p+1][1],
                      bb + (brow + p * 16) * 128 + (cB << 4));
            #pragma unroll
            for (int mt = 0; mt < 2; mt++)
                #pragma unroll
                for (int nt = 0; nt < 8; nt++)
                    mma_f16(acc[mt][nt], a[mt], b[nt]);
        }
    }

    // epilogue
    #pragma unroll
    for (int mt = 0; mt < 2; mt++) {
        const int r0 = bm + wm + mt * 16 + g;
        #pragma unroll
        for (int nt = 0; nt < 8; nt++) {
            const int col = bn + wn + nt * 8 + t * 2;
            const float b0 = bias[col], b1 = bias[col + 1];
            float v0 = acc[mt][nt][0] + b0, v1 = acc[mt][nt][1] + b1;
            float v2 = acc[mt][nt][2] + b0, v3 = acc[mt][nt][3] + b1;
            if (RELU) { v0 = fmaxf(v0, 0.f); v1 = fmaxf(v1, 0.f); v2 = fmaxf(v2, 0.f); v3 = fmaxf(v3, 0.f); }
            if (OUTH) {
                __half* C = (__half*)Cv;
                *reinterpret_cast<__half2*>(C + (size_t)r0 * Nn + col)       = __floats2half2_rn(v0, v1);
                *reinterpret_cast<__half2*>(C + (size_t)(r0 + 8) * Nn + col) = __floats2half2_rn(v2, v3);
            } else {
                float* C = (float*)Cv;
                *reinterpret_cast<float2*>(C + (size_t)r0 * Nn + col)       = make_float2(v0, v1);
                *reinterpret_cast<float2*>(C + (size_t)(r0 + 8) * Nn + col) = make_float2(v2, v3);
            }
        }
    }
}

// ---------------- fp16 tensor-core flash attention -----------------------------
// Row sums via tensor core (ones-B mma). 3 CTAs/SM forced via launch bounds.
static constexpr int ATTN_DSMEM = 49152;

__global__ __launch_bounds__(128, 3)
void attn_h_kernel(const __half* __restrict__ Q, int ldq,
                   const __half* __restrict__ K, int ldk,
                   const __half* __restrict__ V, int ldv,
                   __half* __restrict__ O, int ldo) {
    extern __shared__ char smc[];
    __half* Ps = (__half*)smc;
    const uint32_t sQ = smem_u32(smc);               // Q/P: rows 0..127, 128B rows
    const uint32_t sK = sQ + 16384;                  // K: 2 bufs x 8192B
    const uint32_t sV = sQ + 32768;                  // V: 2 bufs x 8192B

    const int tid = threadIdx.x, lane = tid & 31, wid = tid >> 5;
    const int g = lane >> 2, t = lane & 3;
    const int bh = blockIdx.y, b = bh & 3, h = bh >> 2;
    const int q0 = blockIdx.x * 128;

    #pragma unroll
    for (int i = 0; i < 8; i++) {
        int cl = tid + i * 128, r = cl >> 3, c = cl & 7;
        cp16(sQ + r * 128 + ((c ^ (r & 7)) << 4),
             Q + (size_t)((q0 + r) * BSZ + b) * ldq + h * 64 + c * 8);
    }
    CP_COMMIT();

    auto loadKV = [&](int kt_, int buf_) {
        #pragma unroll
        for (int i = 0; i < 4; i++) {
            int cl = tid + i * 128, r = cl >> 3, c = cl & 7;
            uint32_t off = buf_ * 8192 + r * 128 + ((c ^ (r & 7)) << 4);
            size_t srow = (size_t)((kt_ * 64 + r) * BSZ + b);
            cp16(sK + off, K + srow * ldk + h * 64 + c * 8);
            cp16(sV + off, V + srow * ldv + h * 64 + c * 8);
        }
        CP_COMMIT();
    };
    loadKV(0, 0);

    const int arow = wid * 32 + (lane & 15);
    const int axor = lane & 7;
    const int ach  = (lane >> 4) & 1;
    const int brow = (lane & 7) + ((lane >> 4) & 1) * 8;
    const int bxor = lane & 7;
    const int bch  = (lane >> 3) & 1;
    const int vrow = lane & 15;
    const int vch  = (lane >> 4) & 1;

    CP_WAIT(0);
    __syncthreads();

    // Q fragments; fold the 1/8 softmax scale in once (exact in fp16)
    uint32_t qa[2][4][4];
    {
        const __half2 sc = __float2half2_rn(0.125f);
        #pragma unroll
        for (int mt = 0; mt < 2; mt++)
            #pragma unroll
            for (int ks = 0; ks < 4; ks++) {
                const int c = (2 * ks + ach) ^ axor;
                LDSM4(qa[mt][ks][0], qa[mt][ks][1], qa[mt][ks][2], qa[mt][ks][3],
                      sQ + (arow + mt * 16) * 128 + (c << 4));
                #pragma unroll
                for (int i = 0; i < 4; i++) {
                    __half2 v = __hmul2(*reinterpret_cast<__half2*>(&qa[mt][ks][i]), sc);
                    qa[mt][ks][i] = *reinterpret_cast<uint32_t*>(&v);
                }
            }
    }
    __syncthreads();

    float oacc[2][8][4];
    #pragma unroll
    for (int mt = 0; mt < 2; mt++)
        #pragma unroll
        for (int n = 0; n < 8; n++)
            #pragma unroll
            for (int i = 0; i < 4; i++) oacc[mt][n][i] = 0.0f;
    float lsum[2][4] = {{0.f,0.f,0.f,0.f},{0.f,0.f,0.f,0.f}};
    const uint32_t bone[2] = { 0x3C003C00u, 0x3C003C00u };   // fp16 1.0 x4

    for (int kt = 0; kt < 16; kt++) {
        const int buf = kt & 1;
        if (kt < 15) { loadKV(kt + 1, buf ^ 1); CP_WAIT(1); }
        else         { CP_WAIT(0); }
        __syncthreads();

        const uint32_t kb = sK + buf * 8192;
        const uint32_t vb = sV + buf * 8192;

        #pragma unroll
        for (int half = 0; half < 2; half++) {
            float sacc[2][4][4];
            #pragma unroll
            for (int mt = 0; mt < 2; mt++)
                #pragma unroll
                for (int n = 0; n < 4; n++)
                    #pragma unroll
                    for (int i = 0; i < 4; i++) sacc[mt][n][i] = 0.0f;

            #pragma unroll
            for (int ks = 0; ks < 4; ks++) {
                uint32_t bf[4][2];
                const int c = (2 * ks + bch) ^ bxor;
                #pragma unroll
                for (int p = 0; p < 2; p++) {
                    int row = half * 32 + p * 16 + brow;
                    LDSM4(bf[2*p][0], bf[2*p][1], bf[2*p+1][0], bf[2*p+1][1],
                          kb + row * 128 + (c << 4));
                }
                #pragma unroll
                for (int mt = 0; mt < 2; mt++)
                    #pragma unroll
                    for (int n = 0; n < 4; n++)
                        mma_f16(sacc[mt][n], qa[mt][ks], bf[n]);
            }
            // exp + store P (fp16)
            #pragma unroll
            for (int mt = 0; mt < 2; mt++) {
                const int r0 = wid * 32 + mt * 16 + g;
                #pragma unroll
                for (int n = 0; n < 4; n++) {
                    half2 e01 = h2exp(__floats2half2_rn(sacc[mt][n][0], sacc[mt][n][1]));
                    half2 e23 = h2exp(__floats2half2_rn(sacc[mt][n][2], sacc[mt][n][3]));
                    const int col = half * 32 + n * 8 + 2 * t;
                    const int swz = ((col >> 3) ^ (r0 & 7)) << 3;
                    *reinterpret_cast<__half2*>(Ps + r0 * 64 + swz + (col & 7)) = e01;
                    *reinterpret_cast<__half2*>(Ps + (r0 + 8) * 64 + swz + (col & 7)) = e23;
                }
            }
        }
        __syncwarp();

        #pragma unroll
        for (int ks = 0; ks < 4; ks++) {
            uint32_t pa[2][4];
            const int cA = (2 * ks + ach) ^ axor;
            #pragma unroll
            for (int mt = 0; mt < 2; mt++) {
                LDSM4(pa[mt][0], pa[mt][1], pa[mt][2], pa[mt][3],
                      sQ + (arow + mt * 16) * 128 + (cA << 4));
                mma_f16(lsum[mt], pa[mt], bone);   // row sums on tensor pipe
            }
            #pragma unroll
            for (int dp = 0; dp < 4; dp++) {
                uint32_t bv[4];
                const int row = ks * 16 + vrow;
                const int c = (2 * dp + vch) ^ (vrow & 7);
                LDSM4T(bv[0], bv[1], bv[2], bv[3], vb + row * 128 + (c << 4));
                #pragma unroll
                for (int mt = 0; mt < 2; mt++) {
                    mma_f16(oacc[mt][2*dp],     pa[mt], bv);
                    mma_f16(oacc[mt][2*dp + 1], pa[mt], bv + 2);
                }
            }
        }
        __syncthreads();
    }

    #pragma unroll
    for (int mt = 0; mt < 2; mt++) {
        const float inv0 = 1.0f / lsum[mt][0], inv1 = 1.0f / lsum[mt][2];
        const int r0 = q0 + wid * 32 + mt * 16 + g;
        #pragma unroll
        for (int n = 0; n < 8; n++) {
            const int col = h * 64 + n * 8 + 2 * t;
            *reinterpret_cast<__half2*>(O + (size_t)(r0 * BSZ + b) * ldo + col) =
                __floats2half2_rn(oacc[mt][n][0] * inv0, oacc[mt][n][1] * inv0);
            *reinterpret_cast<__half2*>(O + (size_t)((r0 + 8) * BSZ + b) * ldo + col) =
                __floats2half2_rn(oacc[mt][n][2] * inv1, oacc[mt][n][3] * inv1);
        }
    }
}

// ---------------- Fused residual-add + LayerNorm -------------------------------
__device__ __forceinline__ float block_sum_256(float v, float* red) {
    __syncthreads();
    #pragma unroll
    for (int off = 16; off > 0; off >>= 1) v += __shfl_down_sync(0xffffffffu, v, off);
    int lane = threadIdx.x & 31, w = threadIdx.x >> 5;
    if (lane == 0) red[w] = v;
    __syncthreads();
    if (w == 0) {
        v = (lane < 8) ? red[lane] : 0.0f;
        #pragma unroll
        for (int off = 4; off > 0; off >>= 1) v += __shfl_down_sync(0xffffffffu, v, off);
        if (lane == 0) red[0] = v;
    }
    __syncthreads();
    return red[0];
}

template <int WRITEH>
__global__ __launch_bounds__(256)
void add_ln_kernel(const float* __restrict__ x, const float* __restrict__ y,
                   const float* __restrict__ g, const float* __restrict__ beta,
                   float* __restrict__ out, __half* __restrict__ outh) {
    __shared__ float red[32];
    const int row = blockIdx.x;
    const int tid = threadIdx.x;
    const float* xr = x + (size_t)row * DMODEL;
    const float* yr = y + (size_t)row * DMODEL;

    float v[4];
    float sum = 0.0f;
    #pragma unroll
    for (int i = 0; i < 4; i++) {
        int c = tid + i * 256;
        v[i] = xr[c] + yr[c];
        sum += v[i];
    }
    float mean = block_sum_256(sum, red) * (1.0f / DMODEL);

    float vs = 0.0f;
    #pragma unroll
    for (int i = 0; i < 4; i++) { float d = v[i] - mean; vs += d * d; }
    float var = block_sum_256(vs, red) * (1.0f / DMODEL);
    float rstd = rsqrtf(var + 1e-5f);

    #pragma unroll
    for (int i = 0; i < 4; i++) {
        int c = tid + i * 256;
        float o = (v[i] - mean) * rstd * g[c] + beta[c];
        out[(size_t)row * DMODEL + c] = o;
        if (WRITEH) outh[(size_t)row * DMODEL + c] = __float2half_rn(o);
    }
}

// ---------------- fp32 -> fp16 convert kernels ----------------------------------
__global__ __launch_bounds__(256)
void cvt_h_kernel(const float4* __restrict__ src, __half2* __restrict__ dst, int n4) {
    int i = blockIdx.x * blockDim.x + threadIdx.x;
    if (i < n4) {
        float4 v = src[i];
        dst[2*i]     = __floats2half2_rn(v.x, v.y);
        dst[2*i + 1] = __floats2half2_rn(v.z, v.w);
    }
}

struct CvtJobs {
    const float4* src[6];
    __half2*      dst[6];
    int           off[7];   // cumulative n4 offsets, off[0] = 0
};

__global__ __launch_bounds__(256)
void megacvt_kernel(const __grid_constant__ CvtJobs j, int total) {
    int i = blockIdx.x * blockDim.x + threadIdx.x;
    if (i >= total) return;
    int k = 0;
    #pragma unroll
    for (int s = 1; s < 6; s++) if (i >= j.off[s]) k = s;
    int o = i - j.off[k];
    float4 v = j.src[k][o];
    j.dst[k][2*o]     = __floats2half2_rn(v.x, v.y);
    j.dst[k][2*o + 1] = __floats2half2_rn(v.z, v.w);
}

template <int M>
__global__ __launch_bounds__(256)
void cat_h_kernel(const float4* __restrict__ s0, const float4* __restrict__ s1,
                  const float4* __restrict__ s2, __half2* __restrict__ dst, int n4each,
                  const float* __restrict__ b0, const float* __restrict__ b1,
                  const float* __restrict__ b2, float* __restrict__ bdst, int nbeach) {
    int i = blockIdx.x * blockDim.x + threadIdx.x;
    int tot = M * n4each;
    if (i < tot) {
        int sel = i / n4each, off = i - sel * n4each;
        const float4* s = (sel == 0) ? s0 : ((sel == 1) ? s1 : s2);
        float4 v = s[off];
        dst[2*i]     = __floats2half2_rn(v.x, v.y);
        dst[2*i + 1] = __floats2half2_rn(v.z, v.w);
    } else {
        int j = i - tot;
        if (j < M * nbeach) {
            int sel = j / nbeach, off = j - sel * nbeach;
            const float* b = (sel == 0) ? b0 : ((sel == 1) ? b1 : b2);
            bdst[j] = b[off];
        }
    }
}

// ---------------- host orchestration -------------------------------------------
template <int RELU, int OUTH>
static void launch_gemm(const __half* A, const __half* W, const float* bias,
                        void* C, int M, int N, int K) {
    dim3 grid(N / 128, M / 128);
    gemm_h_kernel<RELU, OUTH><<<grid, 256, GEMM_DSMEM>>>(A, W, bias, C, N, K);
}

extern "C" void kernel_launch(void* const* d_in, const int* in_sizes, int n_in,
                              void* d_out, int out_size) {
    (void)in_sizes; (void)n_in; (void)out_size;

    const float* input = (const float*)d_in[0];
    const float* enc_  = (const float*)d_in[1];
    const float* sa_wq = (const float*)d_in[2];
    const float* sa_bq = (const float*)d_in[3];
    const float* sa_wk = (const float*)d_in[4];
    const float* sa_bk = (const float*)d_in[5];
    const float* sa_wv = (const float*)d_in[6];
    const float* sa_bv = (const float*)d_in[7];
    const float* sa_wo = (const float*)d_in[8];
    const float* sa_bo = (const float*)d_in[9];
    const float* ca_wq = (const float*)d_in[10];
    const float* ca_bq = (const float*)d_in[11];
    const float* ca_wk = (const float*)d_in[12];
    const float* ca_bk = (const float*)d_in[13];
    const float* ca_wv = (const float*)d_in[14];
    const float* ca_bv = (const float*)d_in[15];
    const float* ca_wo = (const float*)d_in[16];
    const float* ca_bo = (const float*)d_in[17];
    const float* w1    = (const float*)d_in[18];
    const float* b1    = (const float*)d_in[19];
    const float* w2    = (const float*)d_in[20];
    const float* b2    = (const float*)d_in[21];
    const float* ln1_g = (const float*)d_in[22];
    const float* ln1_b = (const float*)d_in[23];
    const float* ln2_g = (const float*)d_in[24];
    const float* ln2_b = (const float*)d_in[25];
    const float* ln3_g = (const float*)d_in[26];
    const float* ln3_b = (const float*)d_in[27];
    float* out = (float*)d_out;

    __half *qkvh, *qvh, *kh, *attnh, *ffnh, *rinh, *renh, *x1h, *x2h, *wh;
    float *tmp, *x1, *x2, *bias;
    cudaGetSymbolAddress((void**)&qkvh, g_qkvh);
    cudaGetSymbolAddress((void**)&qvh,  g_qvh);
    cudaGetSymbolAddress((void**)&kh,   g_kh);
    cudaGetSymbolAddress((void**)&attnh,g_attnh);
    cudaGetSymbolAddress((void**)&ffnh, g_ffnh);
    cudaGetSymbolAddress((void**)&rinh, g_rinh);
    cudaGetSymbolAddress((void**)&renh, g_renh);
    cudaGetSymbolAddress((void**)&x1h,  g_x1h);
    cudaGetSymbolAddress((void**)&x2h,  g_x2h);
    cudaGetSymbolAddress((void**)&wh,   g_wh);
    cudaGetSymbolAddress((void**)&tmp,  g_tmp);
    cudaGetSymbolAddress((void**)&x1,   g_x1);
    cudaGetSymbolAddress((void**)&x2,   g_x2);
    cudaGetSymbolAddress((void**)&bias, g_bias);

    cudaFuncSetAttribute(gemm_h_kernel<0,0>, cudaFuncAttributeMaxDynamicSharedMemorySize, GEMM_DSMEM);
    cudaFuncSetAttribute(gemm_h_kernel<0,1>, cudaFuncAttributeMaxDynamicSharedMemorySize, GEMM_DSMEM);
    cudaFuncSetAttribute(gemm_h_kernel<1,1>, cudaFuncAttributeMaxDynamicSharedMemorySize, GEMM_DSMEM);
    cudaFuncSetAttribute(attn_h_kernel, cudaFuncAttributeMaxDynamicSharedMemorySize, ATTN_DSMEM);

    const int MB = 1024 * 1024;
    __half* wh_sa_qkv = wh + 0*MB;
    __half* wh_sa_wo  = wh + 3*MB;
    __half* wh_ca_qv  = wh + 4*MB;
    __half* wh_ca_wk  = wh + 6*MB;
    __half* wh_ca_wo  = wh + 7*MB;
    __half* wh_w1     = wh + 8*MB;
    __half* wh_w2     = wh + 12*MB;
    float* b_sa_qkv = bias;
    float* b_ca_qv  = bias + 4096;

    const int n4w = MB / 4;
    dim3 agrid(SEQ / 128, BSZ * NHEAD);

    // #1: round+concat sa wq|wk|wv (+biases)
    {
        int tot = 3 * n4w + 3 * 1024;
        cat_h_kernel<3><<<(tot + 255) / 256, 256>>>(
            (const float4*)sa_wq, (const float4*)sa_wk, (const float4*)sa_wv,
            (__half2*)wh_sa_qkv, n4w, sa_bq, sa_bk, sa_bv, b_sa_qkv, 1024);
    }
    // #2: convert input (QKV dependency)
    {
        int n4 = MROWS * DMODEL / 4;
        cvt_h_kernel<<<(n4 + 255) / 256, 256>>>((const float4*)input, (__half2*)rinh, n4);
    }
    // #3: QKV GEMM   #4: attention (ncu capture slot)
    launch_gemm<0,1>(rinh, wh_sa_qkv, b_sa_qkv, qkvh, MROWS, 3072, DMODEL);
    attn_h_kernel<<<agrid, 128, ATTN_DSMEM>>>(qkvh, 3072, qkvh + 1024, 3072,
                                              qkvh + 2048, 3072, attnh, 1024);
    // #5: remaining converts   #6: ca concat
    {
        CvtJobs j;
        const float* srcs[6] = { enc_, sa_wo, ca_wk, ca_wo, w1, w2 };
        __half*      dsts[6] = { renh, wh_sa_wo, wh_ca_wk, wh_ca_wo, wh_w1, wh_w2 };
        const int    n4s [6] = { MB, n4w, n4w, n4w, MB, MB };
        int cum = 0;
        for (int s = 0; s < 6; s++) {
            j.src[s] = (const float4*)srcs[s];
            j.dst[s] = (__half2*)dsts[s];
            j.off[s] = cum;
            cum += n4s[s];
        }
        j.off[6] = cum;
        megacvt_kernel<<<(cum + 255) / 256, 256>>>(j, cum);
    }
    {
        int tot = 2 * n4w + 2 * 1024;
        cat_h_kernel<2><<<(tot + 255) / 256, 256>>>(
            (const float4*)ca_wq, (const float4*)ca_wv, nullptr,
            (__half2*)wh_ca_qv, n4w, ca_bq, ca_bv, nullptr, b_ca_qv, 1024);
    }

    // ---- rest of self-attention block ----
    launch_gemm<0,0>(attnh, wh_sa_wo, sa_bo, tmp, MROWS, DMODEL, DMODEL);
    add_ln_kernel<1><<<MROWS, 256>>>(input, tmp, ln1_g, ln1_b, x1, x1h);

    // ---- cross-attention: query=enc, key=x1, value=enc ----
    launch_gemm<0,1>(renh, wh_ca_qv, b_ca_qv, qvh, MROWS, 2048, DMODEL);
    launch_gemm<0,1>(x1h, wh_ca_wk, ca_bk, kh, MROWS, DMODEL, DMODEL);
    attn_h_kernel<<<agrid, 128, ATTN_DSMEM>>>(qvh, 2048, kh, 1024,
                                              qvh + 1024, 2048, attnh, 1024);
    launch_gemm<0,0>(attnh, wh_ca_wo, ca_bo, tmp, MROWS, DMODEL, DMODEL);
    add_ln_kernel<1><<<MROWS, 256>>>(x1, tmp, ln2_g, ln2_b, x2, x2h);

    // ---- FFN ----
    launch_gemm<1,1>(x2h, wh_w1, b1, ffnh, MROWS, DFF_, DMODEL);
    launch_gemm<0,0>(ffnh, wh_w2, b2, tmp, MROWS, DMODEL, DFF_);
    add_ln_kernel<0><<<MROWS, 256>>>(x2, tmp, ln3_g, ln3_b, out, nullptr);
}

// round 13
// speedup vs baseline: 1.0034x; 1.0034x over previous
#include <cuda_runtime.h>
#include <cuda.h>
#include <cuda_fp16.h>
#include <stdint.h>
#include <math.h>

#define SEQ    1024
#define BSZ    4
#define DMODEL 1024
#define NHEAD  16
#define HDIM   64
#define DFF_   4096
#define MROWS  (SEQ*BSZ)

// ---------------- scratch (device globals; no allocation allowed) ------------
__device__ __align__(1024) __half g_qkvh[MROWS*3072];
__device__ __align__(1024) __half g_qvh [MROWS*2048];
__device__ __align__(1024) __half g_kh  [MROWS*DMODEL];
__device__ __align__(1024) __half g_attnh[MROWS*DMODEL];
__device__ __align__(1024) __half g_ffnh[MROWS*DFF_];
__device__ __align__(1024) __half g_rinh[MROWS*DMODEL];
__device__ __align__(1024) __half g_renh[MROWS*DMODEL];
__device__ __align__(1024) __half g_x1h [MROWS*DMODEL];
__device__ __align__(1024) __half g_x2h [MROWS*DMODEL];
__device__ __align__(1024) __half g_wh  [16*1024*1024];
__device__ __align__(1024) float  g_tmp [MROWS*DMODEL];
__device__ __align__(1024) float  g_x1  [MROWS*DMODEL];
__device__ __align__(1024) float  g_x2  [MROWS*DMODEL];
__device__ __align__(1024) float  g_bias[8192];

// ---------------- helpers -------------------------------------------------
__device__ __forceinline__ uint32_t smem_u32(const void* p) {
    uint32_t a;
    asm("{ .reg .u64 t; cvta.to.shared.u64 t, %1; cvt.u32.u64 %0, t; }" : "=r"(a) : "l"(p));
    return a;
}
__device__ __forceinline__ void cp16(uint32_t dst, const void* src) {
    asm volatile("cp.async.cg.shared.global [%0], [%1], 16;" :: "r"(dst), "l"(src));
}
#define CP_COMMIT() asm volatile("cp.async.commit_group;" ::: "memory")
#define CP_WAIT(N)  asm volatile("cp.async.wait_group %0;" :: "n"(N) : "memory")

#define LDSM4(r0, r1, r2, r3, addr) \
    asm volatile("ldmatrix.sync.aligned.m8n8.x4.shared.b16 {%0,%1,%2,%3}, [%4];" \
        : "=r"(r0), "=r"(r1), "=r"(r2), "=r"(r3) : "r"(addr))
#define LDSM4T(r0, r1, r2, r3, addr) \
    asm volatile("ldmatrix.sync.aligned.m8n8.x4.trans.shared.b16 {%0,%1,%2,%3}, [%4];" \
        : "=r"(r0), "=r"(r1), "=r"(r2), "=r"(r3) : "r"(addr))

__device__ __forceinline__ void mma_f16(float c[4], const uint32_t a[4], const uint32_t b[2]) {
    asm volatile(
        "mma.sync.aligned.m16n8k16.row.col.f32.f16.f16.f32 "
        "{%0,%1,%2,%3}, {%4,%5,%6,%7}, {%8,%9}, {%0,%1,%2,%3};"
        : "+f"(c[0]), "+f"(c[1]), "+f"(c[2]), "+f"(c[3])
        : "r"(a[0]), "r"(a[1]), "r"(a[2]), "r"(a[3]), "r"(b[0]), "r"(b[1]));
}

// ---------------- fp16 mma GEMM: C[M,N] = A[M,K] @ W[N,K]^T + bias -----------
// CTA 128x128, 256 threads / 8 warps (4M x 2N), warp tile 32x64, BK=64,
// 3-stage cp.async (2 in flight), XOR-swizzled smem, 2 CTAs/SM.
static constexpr int STAGE_B = 32768;                 // 16KB A + 16KB B
static constexpr int GEMM_DSMEM = 3 * STAGE_B;        // 98304

template <int RELU, int OUTH>
__global__ __launch_bounds__(256, 2)
void gemm_h_kernel(const __half* __restrict__ A, const __half* __restrict__ W,
                   const float* __restrict__ bias, void* __restrict__ Cv,
                   int Nn, int Kn) {
    extern __shared__ char dsmc[];
    const int tid = threadIdx.x, lane = tid & 31, wid = tid >> 5;
    const int g = lane >> 2, t = lane & 3;
    const int bm = blockIdx.y * 128, bn = blockIdx.x * 128;
    const int wm = (wid & 3) * 32, wn = (wid >> 2) * 64;

    float acc[2][8][4];
    #pragma unroll
    for (int mt = 0; mt < 2; mt++)
        #pragma unroll
        for (int nt = 0; nt < 8; nt++)
            #pragma unroll
            for (int i = 0; i < 4; i++) acc[mt][nt][i] = 0.0f;

    const int NIT = Kn / 64;
    const uint32_t sb = smem_u32(dsmc);

    const int lr = tid >> 3, lc = tid & 7;
    auto load_stage = [&](int st, int kk) {
        uint32_t abase = sb + st * STAGE_B;
        uint32_t bbase = abase + 16384;
        #pragma unroll
        for (int p = 0; p < 4; p++) {
            int r = lr + p * 32;
            cp16(abase + r * 128 + ((lc ^ (r & 7)) << 4),
                 A + (size_t)(bm + r) * Kn + kk + lc * 8);
        }
        #pragma unroll
        for (int p = 0; p < 4; p++) {
            int r = lr + p * 32;
            cp16(bbase + r * 128 + ((lc ^ (r & 7)) << 4),
                 W + (size_t)(bn + r) * Kn + kk + lc * 8);
        }
        CP_COMMIT();
    };

    load_stage(0, 0);
    load_stage(1, 64);

    const int arow = wm + (lane & 15);
    const int axor = lane & 7;
    const int ach  = (lane >> 4) & 1;
    const int brow = wn + (lane & 7) + ((lane >> 4) & 1) * 8;
    const int bxor = lane & 7;
    const int bch  = (lane >> 3) & 1;

    for (int it = 0; it < NIT; it++) {
        const int cur = it % 3;
        CP_WAIT(1);
        __syncthreads();
        if (it + 2 < NIT) load_stage((it + 2) % 3, (it + 2) * 64);
        else              CP_COMMIT();

        const uint32_t ab = sb + cur * STAGE_B;
        const uint32_t bb = ab + 16384;

        #pragma unroll
        for (int ks = 0; ks < 4; ks++) {
            uint32_t a[2][4], b[8][2];
            const int cA = (2 * ks + ach) ^ axor;
            const int cB = (2 * ks + bch) ^ bxor;
            #pragma unroll
            for (int mt = 0; mt < 2; mt++)
                LDSM4(a[mt][0], a[mt][1], a[mt][2], a[mt][3],
                      ab + (arow + mt * 16) * 128 + (cA << 4));
            #pragma unroll
            for (int p = 0; p < 4; p++)
                LDSM4(b[2*p][0], b[2*p][1], b[2*p+1][0], b[2*p+1][1],
                      bb + (brow + p * 16) * 128 + (cB << 4));
            #pragma unroll
            for (int mt = 0; mt < 2; mt++)
                #pragma unroll
                for (int nt = 0; nt < 8; nt++)
                    mma_f16(acc[mt][nt], a[mt], b[nt]);
        }
    }

    // epilogue
    #pragma unroll
    for (int mt = 0; mt < 2; mt++) {
        const int r0 = bm + wm + mt * 16 + g;
        #pragma unroll
        for (int nt = 0; nt < 8; nt++) {
            const int col = bn + wn + nt * 8 + t * 2;
            const float b0 = bias[col], b1 = bias[col + 1];
            float v0 = acc[mt][nt][0] + b0, v1 = acc[mt][nt][1] + b1;
            float v2 = acc[mt][nt][2] + b0, v3 = acc[mt][nt][3] + b1;
            if (RELU) { v0 = fmaxf(v0, 0.f); v1 = fmaxf(v1, 0.f); v2 = fmaxf(v2, 0.f); v3 = fmaxf(v3, 0.f); }
            if (OUTH) {
                __half* C = (__half*)Cv;
                *reinterpret_cast<__half2*>(C + (size_t)r0 * Nn + col)       = __floats2half2_rn(v0, v1);
                *reinterpret_cast<__half2*>(C + (size_t)(r0 + 8) * Nn + col) = __floats2half2_rn(v2, v3);
            } else {
                float* C = (float*)Cv;
                *reinterpret_cast<float2*>(C + (size_t)r0 * Nn + col)       = make_float2(v0, v1);
                *reinterpret_cast<float2*>(C + (size_t)(r0 + 8) * Nn + col) = make_float2(v2, v3);
            }
        }
    }
}

// ---------------- fp16 tensor-core flash attention -----------------------------
// P kept entirely in registers: mma C-fragment repacks directly into the A
// fragment of the P.V mma (no smem staging). Row sums via ones-B mma.
static constexpr int ATTN_DSMEM = 49152;

__global__ __launch_bounds__(128)
void attn_h_kernel(const __half* __restrict__ Q, int ldq,
                   const __half* __restrict__ K, int ldk,
                   const __half* __restrict__ V, int ldv,
                   __half* __restrict__ O, int ldo) {
    extern __shared__ char smc[];
    const uint32_t sQ = smem_u32(smc);               // Q staging: 16KB
    const uint32_t sK = sQ + 16384;                  // K: 2 bufs x 8192B
    const uint32_t sV = sQ + 32768;                  // V: 2 bufs x 8192B

    const int tid = threadIdx.x, lane = tid & 31, wid = tid >> 5;
    const int bh = blockIdx.y, b = bh & 3, h = bh >> 2;
    const int q0 = blockIdx.x * 128;

    #pragma unroll
    for (int i = 0; i < 8; i++) {
        int cl = tid + i * 128, r = cl >> 3, c = cl & 7;
        cp16(sQ + r * 128 + ((c ^ (r & 7)) << 4),
             Q + (size_t)((q0 + r) * BSZ + b) * ldq + h * 64 + c * 8);
    }
    CP_COMMIT();

    auto loadKV = [&](int kt_, int buf_) {
        #pragma unroll
        for (int i = 0; i < 4; i++) {
            int cl = tid + i * 128, r = cl >> 3, c = cl & 7;
            uint32_t off = buf_ * 8192 + r * 128 + ((c ^ (r & 7)) << 4);
            size_t srow = (size_t)((kt_ * 64 + r) * BSZ + b);
            cp16(sK + off, K + srow * ldk + h * 64 + c * 8);
            cp16(sV + off, V + srow * ldv + h * 64 + c * 8);
        }
        CP_COMMIT();
    };
    loadKV(0, 0);

    const int arow = wid * 32 + (lane & 15);
    const int axor = lane & 7;
    const int ach  = (lane >> 4) & 1;
    const int brow = (lane & 7) + ((lane >> 4) & 1) * 8;
    const int bxor = lane & 7;
    const int bch  = (lane >> 3) & 1;
    const int vrow = lane & 15;
    const int vch  = (lane >> 4) & 1;

    CP_WAIT(0);
    __syncthreads();

    // Q fragments; fold the 1/8 softmax scale in once (exact in fp16)
    uint32_t qa[2][4][4];
    {
        const __half2 sc = __float2half2_rn(0.125f);
        #pragma unroll
        for (int mt = 0; mt < 2; mt++)
            #pragma unroll
            for (int ks = 0; ks < 4; ks++) {
                const int c = (2 * ks + ach) ^ axor;
                LDSM4(qa[mt][ks][0], qa[mt][ks][1], qa[mt][ks][2], qa[mt][ks][3],
                      sQ + (arow + mt * 16) * 128 + (c << 4));
                #pragma unroll
                for (int i = 0; i < 4; i++) {
                    __half2 v = __hmul2(*reinterpret_cast<__half2*>(&qa[mt][ks][i]), sc);
                    qa[mt][ks][i] = *reinterpret_cast<uint32_t*>(&v);
                }
            }
    }

    float oacc[2][8][4];
    #pragma unroll
    for (int mt = 0; mt < 2; mt++)
        #pragma unroll
        for (int n = 0; n < 8; n++)
            #pragma unroll
            for (int i = 0; i < 4; i++) oacc[mt][n][i] = 0.0f;
    float lsum[2][4] = {{0.f,0.f,0.f,0.f},{0.f,0.f,0.f,0.f}};
    const uint32_t bone[2] = { 0x3C003C00u, 0x3C003C00u };   // fp16 1.0 x4

    for (int kt = 0; kt < 16; kt++) {
        const int buf = kt & 1;
        if (kt < 15) { loadKV(kt + 1, buf ^ 1); CP_WAIT(1); }
        else         { CP_WAIT(0); }
        __syncthreads();

        const uint32_t kb = sK + buf * 8192;
        const uint32_t vb = sV + buf * 8192;

        // P fragments for P.V, built directly from S mma outputs (no smem)
        uint32_t pa[2][4][4];

        #pragma unroll
        for (int half = 0; half < 2; half++) {
            float sacc[2][4][4];
            #pragma unroll
            for (int mt = 0; mt < 2; mt++)
                #pragma unroll
                for (int n = 0; n < 4; n++)
                    #pragma unroll
                    for (int i = 0; i < 4; i++) sacc[mt][n][i] = 0.0f;

            #pragma unroll
            for (int ks = 0; ks < 4; ks++) {
                uint32_t bf[4][2];
                const int c = (2 * ks + bch) ^ bxor;
                #pragma unroll
                for (int p = 0; p < 2; p++) {
                    int row = half * 32 + p * 16 + brow;
                    LDSM4(bf[2*p][0], bf[2*p][1], bf[2*p+1][0], bf[2*p+1][1],
                          kb + row * 128 + (c << 4));
                }
                #pragma unroll
                for (int mt = 0; mt < 2; mt++)
                    #pragma unroll
                    for (int n = 0; n < 4; n++)
                        mma_f16(sacc[mt][n], qa[mt][ks], bf[n]);
            }
            // exp -> pa fragments (C layout == A layout pairing)
            // k-chunk j = 2*half + (n>>1); regs: n even -> a0,a1; n odd -> a2,a3
            #pragma unroll
            for (int mt = 0; mt < 2; mt++) {
                #pragma unroll
                for (int n = 0; n < 4; n++) {
                    half2 e01 = h2exp(__floats2half2_rn(sacc[mt][n][0], sacc[mt][n][1]));
                    half2 e23 = h2exp(__floats2half2_rn(sacc[mt][n][2], sacc[mt][n][3]));
                    const int j = 2 * half + (n >> 1);
                    const int r = (n & 1) * 2;
                    pa[mt][j][r]     = *reinterpret_cast<uint32_t*>(&e01);
                    pa[mt][j][r + 1] = *reinterpret_cast<uint32_t*>(&e23);
                }
            }
        }

        // ---- O += P V  (P from registers; V k-major via ldmatrix.trans) ----
        #pragma unroll
        for (int ks = 0; ks < 4; ks++) {
            #pragma unroll
            for (int mt = 0; mt < 2; mt++)
                mma_f16(lsum[mt], pa[mt][ks], bone);   // row sums on tensor pipe
            #pragma unroll
            for (int dp = 0; dp < 4; dp++) {
                uint32_t bv[4];
                const int row = ks * 16 + vrow;
                const int c = (2 * dp + vch) ^ (vrow & 7);
                LDSM4T(bv[0], bv[1], bv[2], bv[3], vb + row * 128 + (c << 4));
                #pragma unroll
                for (int mt = 0; mt < 2; mt++) {
                    mma_f16(oacc[mt][2*dp],     pa[mt][ks], bv);
                    mma_f16(oacc[mt][2*dp + 1], pa[mt][ks], bv + 2);
                }
            }
        }
        __syncthreads();
    }

    const int g = lane >> 2, t = lane & 3;
    #pragma unroll
    for (int mt = 0; mt < 2; mt++) {
        const float inv0 = 1.0f / lsum[mt][0], inv1 = 1.0f / lsum[mt][2];
        const int r0 = q0 + wid * 32 + mt * 16 + g;
        #pragma unroll
        for (int n = 0; n < 8; n++) {
            const int col = h * 64 + n * 8 + 2 * t;
            *reinterpret_cast<__half2*>(O + (size_t)(r0 * BSZ + b) * ldo + col) =
                __floats2half2_rn(oacc[mt][n][0] * inv0, oacc[mt][n][1] * inv0);
            *reinterpret_cast<__half2*>(O + (size_t)((r0 + 8) * BSZ + b) * ldo + col) =
                __floats2half2_rn(oacc[mt][n][2] * inv1, oacc[mt][n][3] * inv1);
        }
    }
}

// ---------------- Fused residual-add + LayerNorm -------------------------------
__device__ __forceinline__ float block_sum_256(float v, float* red) {
    __syncthreads();
    #pragma unroll
    for (int off = 16; off > 0; off >>= 1) v += __shfl_down_sync(0xffffffffu, v, off);
    int lane = threadIdx.x & 31, w = threadIdx.x >> 5;
    if (lane == 0) red[w] = v;
    __syncthreads();
    if (w == 0) {
        v = (lane < 8) ? red[lane] : 0.0f;
        #pragma unroll
        for (int off = 4; off > 0; off >>= 1) v += __shfl_down_sync(0xffffffffu, v, off);
        if (lane == 0) red[0] = v;
    }
    __syncthreads();
    return red[0];
}

template <int WRITEH>
__global__ __launch_bounds__(256)
void add_ln_kernel(const float* __restrict__ x, const float* __restrict__ y,
                   const float* __restrict__ g, const float* __restrict__ beta,
                   float* __restrict__ out, __half* __restrict__ outh) {
    __shared__ float red[32];
    const int row = blockIdx.x;
    const int tid = threadIdx.x;
    const float* xr = x + (size_t)row * DMODEL;
    const float* yr = y + (size_t)row * DMODEL;

    float v[4];
    float sum = 0.0f;
    #pragma unroll
    for (int i = 0; i < 4; i++) {
        int c = tid + i * 256;
        v[i] = xr[c] + yr[c];
        sum += v[i];
    }
    float mean = block_sum_256(sum, red) * (1.0f / DMODEL);

    float vs = 0.0f;
    #pragma unroll
    for (int i = 0; i < 4; i++) { float d = v[i] - mean; vs += d * d; }
    float var = block_sum_256(vs, red) * (1.0f / DMODEL);
    float rstd = rsqrtf(var + 1e-5f);

    #pragma unroll
    for (int i = 0; i < 4; i++) {
        int c = tid + i * 256;
        float o = (v[i] - mean) * rstd * g[c] + beta[c];
        out[(size_t)row * DMODEL + c] = o;
        if (WRITEH) outh[(size_t)row * DMODEL + c] = __float2half_rn(o);
    }
}

// ---------------- fp32 -> fp16 convert kernels ----------------------------------
__global__ __launch_bounds__(256)
void cvt_h_kernel(const float4* __restrict__ src, __half2* __restrict__ dst, int n4) {
    int i = blockIdx.x * blockDim.x + threadIdx.x;
    if (i < n4) {
        float4 v = src[i];
        dst[2*i]     = __floats2half2_rn(v.x, v.y);
        dst[2*i + 1] = __floats2half2_rn(v.z, v.w);
    }
}

struct CvtJobs {
    const float4* src[6];
    __half2*      dst[6];
    int           off[7];   // cumulative n4 offsets, off[0] = 0
};

__global__ __launch_bounds__(256)
void megacvt_kernel(const __grid_constant__ CvtJobs j, int total) {
    int i = blockIdx.x * blockDim.x + threadIdx.x;
    if (i >= total) return;
    int k = 0;
    #pragma unroll
    for (int s = 1; s < 6; s++) if (i >= j.off[s]) k = s;
    int o = i - j.off[k];
    float4 v = j.src[k][o];
    j.dst[k][2*o]     = __floats2half2_rn(v.x, v.y);
    j.dst[k][2*o + 1] = __floats2half2_rn(v.z, v.w);
}

template <int M>
__global__ __launch_bounds__(256)
void cat_h_kernel(const float4* __restrict__ s0, const float4* __restrict__ s1,
                  const float4* __restrict__ s2, __half2* __restrict__ dst, int n4each,
                  const float* __restrict__ b0, const float* __restrict__ b1,
                  const float* __restrict__ b2, float* __restrict__ bdst, int nbeach) {
    int i = blockIdx.x * blockDim.x + threadIdx.x;
    int tot = M * n4each;
    if (i < tot) {
        int sel = i / n4each, off = i - sel * n4each;
        const float4* s = (sel == 0) ? s0 : ((sel == 1) ? s1 : s2);
        float4 v = s[off];
        dst[2*i]     = __floats2half2_rn(v.x, v.y);
        dst[2*i + 1] = __floats2half2_rn(v.z, v.w);
    } else {
        int j = i - tot;
        if (j < M * nbeach) {
            int sel = j / nbeach, off = j - sel * nbeach;
            const float* b = (sel == 0) ? b0 : ((sel == 1) ? b1 : b2);
            bdst[j] = b[off];
        }
    }
}

// ---------------- host orchestration -------------------------------------------
template <int RELU, int OUTH>
static void launch_gemm(const __half* A, const __half* W, const float* bias,
                        void* C, int M, int N, int K) {
    dim3 grid(N / 128, M / 128);
    gemm_h_kernel<RELU, OUTH><<<grid, 256, GEMM_DSMEM>>>(A, W, bias, C, N, K);
}

extern "C" void kernel_launch(void* const* d_in, const int* in_sizes, int n_in,
                              void* d_out, int out_size) {
    (void)in_sizes; (void)n_in; (void)out_size;

    const float* input = (const float*)d_in[0];
    const float* enc_  = (const float*)d_in[1];
    const float* sa_wq = (const float*)d_in[2];
    const float* sa_bq = (const float*)d_in[3];
    const float* sa_wk = (const float*)d_in[4];
    const float* sa_bk = (const float*)d_in[5];
    const float* sa_wv = (const float*)d_in[6];
    const float* sa_bv = (const float*)d_in[7];
    const float* sa_wo = (const float*)d_in[8];
    const float* sa_bo = (const float*)d_in[9];
    const float* ca_wq = (const float*)d_in[10];
    const float* ca_bq = (const float*)d_in[11];
    const float* ca_wk = (const float*)d_in[12];
    const float* ca_bk = (const float*)d_in[13];
    const float* ca_wv = (const float*)d_in[14];
    const float* ca_bv = (const float*)d_in[15];
    const float* ca_wo = (const float*)d_in[16];
    const float* ca_bo = (const float*)d_in[17];
    const float* w1    = (const float*)d_in[18];
    const float* b1    = (const float*)d_in[19];
    const float* w2    = (const float*)d_in[20];
    const float* b2    = (const float*)d_in[21];
    const float* ln1_g = (const float*)d_in[22];
    const float* ln1_b = (const float*)d_in[23];
    const float* ln2_g = (const float*)d_in[24];
    const float* ln2_b = (const float*)d_in[25];
    const float* ln3_g = (const float*)d_in[26];
    const float* ln3_b = (const float*)d_in[27];
    float* out = (float*)d_out;

    __half *qkvh, *qvh, *kh, *attnh, *ffnh, *rinh, *renh, *x1h, *x2h, *wh;
    float *tmp, *x1, *x2, *bias;
    cudaGetSymbolAddress((void**)&qkvh, g_qkvh);
    cudaGetSymbolAddress((void**)&qvh,  g_qvh);
    cudaGetSymbolAddress((void**)&kh,   g_kh);
    cudaGetSymbolAddress((void**)&attnh,g_attnh);
    cudaGetSymbolAddress((void**)&ffnh, g_ffnh);
    cudaGetSymbolAddress((void**)&rinh, g_rinh);
    cudaGetSymbolAddress((void**)&renh, g_renh);
    cudaGetSymbolAddress((void**)&x1h,  g_x1h);
    cudaGetSymbolAddress((void**)&x2h,  g_x2h);
    cudaGetSymbolAddress((void**)&wh,   g_wh);
    cudaGetSymbolAddress((void**)&tmp,  g_tmp);
    cudaGetSymbolAddress((void**)&x1,   g_x1);
    cudaGetSymbolAddress((void**)&x2,   g_x2);
    cudaGetSymbolAddress((void**)&bias, g_bias);

    cudaFuncSetAttribute(gemm_h_kernel<0,0>, cudaFuncAttributeMaxDynamicSharedMemorySize, GEMM_DSMEM);
    cudaFuncSetAttribute(gemm_h_kernel<0,1>, cudaFuncAttributeMaxDynamicSharedMemorySize, GEMM_DSMEM);
    cudaFuncSetAttribute(gemm_h_kernel<1,1>, cudaFuncAttributeMaxDynamicSharedMemorySize, GEMM_DSMEM);
    cudaFuncSetAttribute(attn_h_kernel, cudaFuncAttributeMaxDynamicSharedMemorySize, ATTN_DSMEM);

    const int MB = 1024 * 1024;
    __half* wh_sa_qkv = wh + 0*MB;
    __half* wh_sa_wo  = wh + 3*MB;
    __half* wh_ca_qv  = wh + 4*MB;
    __half* wh_ca_wk  = wh + 6*MB;
    __half* wh_ca_wo  = wh + 7*MB;
    __half* wh_w1     = wh + 8*MB;
    __half* wh_w2     = wh + 12*MB;
    float* b_sa_qkv = bias;
    float* b_ca_qv  = bias + 4096;

    const int n4w = MB / 4;
    dim3 agrid(SEQ / 128, BSZ * NHEAD);

    // #1: round+concat sa wq|wk|wv (+biases)
    {
        int tot = 3 * n4w + 3 * 1024;
        cat_h_kernel<3><<<(tot + 255) / 256, 256>>>(
            (const float4*)sa_wq, (const float4*)sa_wk, (const float4*)sa_wv,
            (__half2*)wh_sa_qkv, n4w, sa_bq, sa_bk, sa_bv, b_sa_qkv, 1024);
    }
    // #2: convert input (QKV dependency)
    {
        int n4 = MROWS * DMODEL / 4;
        cvt_h_kernel<<<(n4 + 255) / 256, 256>>>((const float4*)input, (__half2*)rinh, n4);
    }
    // #3: QKV GEMM   #4: attention (ncu capture slot)
    launch_gemm<0,1>(rinh, wh_sa_qkv, b_sa_qkv, qkvh, MROWS, 3072, DMODEL);
    attn_h_kernel<<<agrid, 128, ATTN_DSMEM>>>(qkvh, 3072, qkvh + 1024, 3072,
                                              qkvh + 2048, 3072, attnh, 1024);
    // #5: remaining converts   #6: ca concat
    {
        CvtJobs j;
        const float* srcs[6] = { enc_, sa_wo, ca_wk, ca_wo, w1, w2 };
        __half*      dsts[6] = { renh, wh_sa_wo, wh_ca_wk, wh_ca_wo, wh_w1, wh_w2 };
        const int    n4s [6] = { MB, n4w, n4w, n4w, MB, MB };
        int cum = 0;
        for (int s = 0; s < 6; s++) {
            j.src[s] = (const float4*)srcs[s];
            j.dst[s] = (__half2*)dsts[s];
            j.off[s] = cum;
            cum += n4s[s];
        }
        j.off[6] = cum;
        megacvt_kernel<<<(cum + 255) / 256, 256>>>(j, cum);
    }
    {
        int tot = 2 * n4w + 2 * 1024;
        cat_h_kernel<2><<<(tot + 255) / 256, 256>>>(
            (const float4*)ca_wq, (const float4*)ca_wv, nullptr,
            (__half2*)wh_ca_qv, n4w, ca_bq, ca_bv, nullptr, b_ca_qv, 1024);
    }

    // ---- rest of self-attention block ----
    launch_gemm<0,0>(attnh, wh_sa_wo, sa_bo, tmp, MROWS, DMODEL, DMODEL);
    add_ln_kernel<1><<<MROWS, 256>>>(input, tmp, ln1_g, ln1_b, x1, x1h);

    // ---- cross-attention: query=enc, key=x1, value=enc ----
    launch_gemm<0,1>(renh, wh_ca_qv, b_ca_qv, qvh, MROWS, 2048, DMODEL);
    launch_gemm<0,1>(x1h, wh_ca_wk, ca_bk, kh, MROWS, DMODEL, DMODEL);
    attn_h_kernel<<<agrid, 128, ATTN_DSMEM>>>(qvh, 2048, kh, 1024,
                                              qvh + 1024, 2048, attnh, 1024);
    launch_gemm<0,0>(attnh, wh_ca_wo, ca_bo, tmp, MROWS, DMODEL, DMODEL);
    add_ln_kernel<1><<<MROWS, 256>>>(x1, tmp, ln2_g, ln2_b, x2, x2h);

    // ---- FFN ----
    launch_gemm<1,1>(x2h, wh_w1, b1, ffnh, MROWS, DFF_, DMODEL);
    launch_gemm<0,0>(ffnh, wh_w2, b2, tmp, MROWS, DMODEL, DFF_);
    add_ln_kernel<0><<<MROWS, 256>>>(x2, tmp, ln3_g, ln3_b, out, nullptr);
}

// round 14
// speedup vs baseline: 1.0062x; 1.0028x over previous
#include <cuda_runtime.h>
#include <cuda.h>
#include <cuda_fp16.h>
#include <stdint.h>
#include <math.h>

#define SEQ    1024
#define BSZ    4
#define DMODEL 1024
#define NHEAD  16
#define HDIM   64
#define DFF_   4096
#define MROWS  (SEQ*BSZ)

// ---------------- scratch (device globals; no allocation allowed) ------------
__device__ __align__(1024) __half g_qkvh[MROWS*3072];
__device__ __align__(1024) __half g_qvh [MROWS*2048];
__device__ __align__(1024) __half g_kh  [MROWS*DMODEL];
__device__ __align__(1024) __half g_attnh[MROWS*DMODEL];
__device__ __align__(1024) __half g_ffnh[MROWS*DFF_];
__device__ __align__(1024) __half g_rinh[MROWS*DMODEL];
__device__ __align__(1024) __half g_renh[MROWS*DMODEL];
__device__ __align__(1024) __half g_x1h [MROWS*DMODEL];
__device__ __align__(1024) __half g_x2h [MROWS*DMODEL];
__device__ __align__(1024) __half g_wh  [16*1024*1024];
__device__ __align__(1024) float  g_tmp [MROWS*DMODEL];
__device__ __align__(1024) float  g_x1  [MROWS*DMODEL];
__device__ __align__(1024) float  g_x2  [MROWS*DMODEL];
__device__ __align__(1024) float  g_bias[8192];

// ---------------- helpers -------------------------------------------------
__device__ __forceinline__ uint32_t smem_u32(const void* p) {
    uint32_t a;
    asm("{ .reg .u64 t; cvta.to.shared.u64 t, %1; cvt.u32.u64 %0, t; }" : "=r"(a) : "l"(p));
    return a;
}
__device__ __forceinline__ void cp16(uint32_t dst, const void* src) {
    asm volatile("cp.async.cg.shared.global [%0], [%1], 16;" :: "r"(dst), "l"(src));
}
#define CP_COMMIT() asm volatile("cp.async.commit_group;" ::: "memory")
#define CP_WAIT(N)  asm volatile("cp.async.wait_group %0;" :: "n"(N) : "memory")

#define LDSM4(r0, r1, r2, r3, addr) \
    asm volatile("ldmatrix.sync.aligned.m8n8.x4.shared.b16 {%0,%1,%2,%3}, [%4];" \
        : "=r"(r0), "=r"(r1), "=r"(r2), "=r"(r3) : "r"(addr))
#define LDSM4T(r0, r1, r2, r3, addr) \
    asm volatile("ldmatrix.sync.aligned.m8n8.x4.trans.shared.b16 {%0,%1,%2,%3}, [%4];" \
        : "=r"(r0), "=r"(r1), "=r"(r2), "=r"(r3) : "r"(addr))

__device__ __forceinline__ void mma_f16(float c[4], const uint32_t a[4], const uint32_t b[2]) {
    asm volatile(
        "mma.sync.aligned.m16n8k16.row.col.f32.f16.f16.f32 "
        "{%0,%1,%2,%3}, {%4,%5,%6,%7}, {%8,%9}, {%0,%1,%2,%3};"
        : "+f"(c[0]), "+f"(c[1]), "+f"(c[2]), "+f"(c[3])
        : "r"(a[0]), "r"(a[1]), "r"(a[2]), "r"(a[3]), "r"(b[0]), "r"(b[1]));
}

// ---------------- fp16 mma GEMM: C[M,N] = A[M,K] @ W[N,K]^T + bias -----------
// CTA 128x128, 256 threads / 8 warps (4M x 2N), warp tile 32x64, BK=64,
// 3-stage cp.async (2 in flight), XOR-swizzled smem, 2 CTAs/SM.
static constexpr int STAGE_B = 32768;                 // 16KB A + 16KB B
static constexpr int GEMM_DSMEM = 3 * STAGE_B;        // 98304

template <int RELU, int OUTH>
__global__ __launch_bounds__(256, 2)
void gemm_h_kernel(const __half* __restrict__ A, const __half* __restrict__ W,
                   const float* __restrict__ bias, void* __restrict__ Cv,
                   int Nn, int Kn) {
    extern __shared__ char dsmc[];
    const int tid = threadIdx.x, lane = tid & 31, wid = tid >> 5;
    const int g = lane >> 2, t = lane & 3;
    const int bm = blockIdx.y * 128, bn = blockIdx.x * 128;
    const int wm = (wid & 3) * 32, wn = (wid >> 2) * 64;

    float acc[2][8][4];
    #pragma unroll
    for (int mt = 0; mt < 2; mt++)
        #pragma unroll
        for (int nt = 0; nt < 8; nt++)
            #pragma unroll
            for (int i = 0; i < 4; i++) acc[mt][nt][i] = 0.0f;

    const int NIT = Kn / 64;
    const uint32_t sb = smem_u32(dsmc);

    const int lr = tid >> 3, lc = tid & 7;
    auto load_stage = [&](int st, int kk) {
        uint32_t abase = sb + st * STAGE_B;
        uint32_t bbase = abase + 16384;
        #pragma unroll
        for (int p = 0; p < 4; p++) {
            int r = lr + p * 32;
            cp16(abase + r * 128 + ((lc ^ (r & 7)) << 4),
                 A + (size_t)(bm + r) * Kn + kk + lc * 8);
        }
        #pragma unroll
        for (int p = 0; p < 4; p++) {
            int r = lr + p * 32;
            cp16(bbase + r * 128 + ((lc ^ (r & 7)) << 4),
                 W + (size_t)(bn + r) * Kn + kk + lc * 8);
        }
        CP_COMMIT();
    };

    load_stage(0, 0);
    load_stage(1, 64);

    const int arow = wm + (lane & 15);
    const int axor = lane & 7;
    const int ach  = (lane >> 4) & 1;
    const int brow = wn + (lane & 7) + ((lane >> 4) & 1) * 8;
    const int bxor = lane & 7;
    const int bch  = (lane >> 3) & 1;

    for (int it = 0; it < NIT; it++) {
        const int cur = it % 3;
        CP_WAIT(1);
        __syncthreads();
        if (it + 2 < NIT) load_stage((it + 2) % 3, (it + 2) * 64);
        else              CP_COMMIT();

        const uint32_t ab = sb + cur * STAGE_B;
        const uint32_t bb = ab + 16384;

        #pragma unroll
        for (int ks = 0; ks < 4; ks++) {
            uint32_t a[2][4], b[8][2];
            const int cA = (2 * ks + ach) ^ axor;
            const int cB = (2 * ks + bch) ^ bxor;
            #pragma unroll
            for (int mt = 0; mt < 2; mt++)
                LDSM4(a[mt][0], a[mt][1], a[mt][2], a[mt][3],
                      ab + (arow + mt * 16) * 128 + (cA << 4));
            #pragma unroll
            for (int p = 0; p < 4; p++)
                LDSM4(b[2*p][0], b[2*p][1], b[2*p+1][0], b[2*p+1][1],
                      bb + (brow + p * 16) * 128 + (cB << 4));
            #pragma unroll
            for (int mt = 0; mt < 2; mt++)
                #pragma unroll
                for (int nt = 0; nt < 8; nt++)
                    mma_f16(acc[mt][nt], a[mt], b[nt]);
        }
    }

    // epilogue
    #pragma unroll
    for (int mt = 0; mt < 2; mt++) {
        const int r0 = bm + wm + mt * 16 + g;
        #pragma unroll
        for (int nt = 0; nt < 8; nt++) {
            const int col = bn + wn + nt * 8 + t * 2;
            const float b0 = bias[col], b1 = bias[col + 1];
            float v0 = acc[mt][nt][0] + b0, v1 = acc[mt][nt][1] + b1;
            float v2 = acc[mt][nt][2] + b0, v3 = acc[mt][nt][3] + b1;
            if (RELU) { v0 = fmaxf(v0, 0.f); v1 = fmaxf(v1, 0.f); v2 = fmaxf(v2, 0.f); v3 = fmaxf(v3, 0.f); }
            if (OUTH) {
                __half* C = (__half*)Cv;
                *reinterpret_cast<__half2*>(C + (size_t)r0 * Nn + col)       = __floats2half2_rn(v0, v1);
                *reinterpret_cast<__half2*>(C + (size_t)(r0 + 8) * Nn + col) = __floats2half2_rn(v2, v3);
            } else {
                float* C = (float*)Cv;
                *reinterpret_cast<float2*>(C + (size_t)r0 * Nn + col)       = make_float2(v0, v1);
                *reinterpret_cast<float2*>(C + (size_t)(r0 + 8) * Nn + col) = make_float2(v2, v3);
            }
        }
    }
}

// ---------------- fp16 tensor-core flash attention -----------------------------
// P kept entirely in registers: mma C-fragment repacks directly into the A
// fragment of the P.V mma (no smem staging). Row sums via ones-B mma.
static constexpr int ATTN_DSMEM = 49152;

__global__ __launch_bounds__(128)
void attn_h_kernel(const __half* __restrict__ Q, int ldq,
                   const __half* __restrict__ K, int ldk,
                   const __half* __restrict__ V, int ldv,
                   __half* __restrict__ O, int ldo) {
    extern __shared__ char smc[];
    const uint32_t sQ = smem_u32(smc);               // Q staging: 16KB
    const uint32_t sK = sQ + 16384;                  // K: 2 bufs x 8192B
    const uint32_t sV = sQ + 32768;                  // V: 2 bufs x 8192B

    const int tid = threadIdx.x, lane = tid & 31, wid = tid >> 5;
    const int bh = blockIdx.y, b = bh & 3, h = bh >> 2;
    const int q0 = blockIdx.x * 128;

    #pragma unroll
    for (int i = 0; i < 8; i++) {
        int cl = tid + i * 128, r = cl >> 3, c = cl & 7;
        cp16(sQ + r * 128 + ((c ^ (r & 7)) << 4),
             Q + (size_t)((q0 + r) * BSZ + b) * ldq + h * 64 + c * 8);
    }
    CP_COMMIT();

    auto loadKV = [&](int kt_, int buf_) {
        #pragma unroll
        for (int i = 0; i < 4; i++) {
            int cl = tid + i * 128, r = cl >> 3, c = cl & 7;
            uint32_t off = buf_ * 8192 + r * 128 + ((c ^ (r & 7)) << 4);
            size_t srow = (size_t)((kt_ * 64 + r) * BSZ + b);
            cp16(sK + off, K + srow * ldk + h * 64 + c * 8);
            cp16(sV + off, V + srow * ldv + h * 64 + c * 8);
        }
        CP_COMMIT();
    };
    loadKV(0, 0);

    const int arow = wid * 32 + (lane & 15);
    const int axor = lane & 7;
    const int ach  = (lane >> 4) & 1;
    const int brow = (lane & 7) + ((lane >> 4) & 1) * 8;
    const int bxor = lane & 7;
    const int bch  = (lane >> 3) & 1;
    const int vrow = lane & 15;
    const int vch  = (lane >> 4) & 1;

    CP_WAIT(0);
    __syncthreads();

    // Q fragments; fold the 1/8 softmax scale in once (exact in fp16)
    uint32_t qa[2][4][4];
    {
        const __half2 sc = __float2half2_rn(0.125f);
        #pragma unroll
        for (int mt = 0; mt < 2; mt++)
            #pragma unroll
            for (int ks = 0; ks < 4; ks++) {
                const int c = (2 * ks + ach) ^ axor;
                LDSM4(qa[mt][ks][0], qa[mt][ks][1], qa[mt][ks][2], qa[mt][ks][3],
                      sQ + (arow + mt * 16) * 128 + (c << 4));
                #pragma unroll
                for (int i = 0; i < 4; i++) {
                    __half2 v = __hmul2(*reinterpret_cast<__half2*>(&qa[mt][ks][i]), sc);
                    qa[mt][ks][i] = *reinterpret_cast<uint32_t*>(&v);
                }
            }
    }

    float oacc[2][8][4];
    #pragma unroll
    for (int mt = 0; mt < 2; mt++)
        #pragma unroll
        for (int n = 0; n < 8; n++)
            #pragma unroll
            for (int i = 0; i < 4; i++) oacc[mt][n][i] = 0.0f;
    float lsum[2][4] = {{0.f,0.f,0.f,0.f},{0.f,0.f,0.f,0.f}};
    const uint32_t bone[2] = { 0x3C003C00u, 0x3C003C00u };   // fp16 1.0 x4

    for (int kt = 0; kt < 16; kt++) {
        const int buf = kt & 1;
        if (kt < 15) { loadKV(kt + 1, buf ^ 1); CP_WAIT(1); }
        else         { CP_WAIT(0); }
        __syncthreads();

        const uint32_t kb = sK + buf * 8192;
        const uint32_t vb = sV + buf * 8192;

        // P fragments for P.V, built directly from S mma outputs (no smem)
        uint32_t pa[2][4][4];

        #pragma unroll
        for (int half = 0; half < 2; half++) {
            float sacc[2][4][4];
            #pragma unroll
            for (int mt = 0; mt < 2; mt++)
                #pragma unroll
                for (int n = 0; n < 4; n++)
                    #pragma unroll
                    for (int i = 0; i < 4; i++) sacc[mt][n][i] = 0.0f;

            #pragma unroll
            for (int ks = 0; ks < 4; ks++) {
                uint32_t bf[4][2];
                const int c = (2 * ks + bch) ^ bxor;
                #pragma unroll
                for (int p = 0; p < 2; p++) {
                    int row = half * 32 + p * 16 + brow;
                    LDSM4(bf[2*p][0], bf[2*p][1], bf[2*p+1][0], bf[2*p+1][1],
                          kb + row * 128 + (c << 4));
                }
                #pragma unroll
                for (int mt = 0; mt < 2; mt++)
                    #pragma unroll
                    for (int n = 0; n < 4; n++)
                        mma_f16(sacc[mt][n], qa[mt][ks], bf[n]);
            }
            // exp -> pa fragments (C layout == A layout pairing)
            #pragma unroll
            for (int mt = 0; mt < 2; mt++) {
                #pragma unroll
                for (int n = 0; n < 4; n++) {
                    half2 e01 = h2exp(__floats2half2_rn(sacc[mt][n][0], sacc[mt][n][1]));
                    half2 e23 = h2exp(__floats2half2_rn(sacc[mt][n][2], sacc[mt][n][3]));
                    const int j = 2 * half + (n >> 1);
                    const int r = (n & 1) * 2;
                    pa[mt][j][r]     = *reinterpret_cast<uint32_t*>(&e01);
                    pa[mt][j][r + 1] = *reinterpret_cast<uint32_t*>(&e23);
                }
            }
        }

        // ---- O += P V  (P from registers; V k-major via ldmatrix.trans) ----
        #pragma unroll
        for (int ks = 0; ks < 4; ks++) {
            #pragma unroll
            for (int mt = 0; mt < 2; mt++)
                mma_f16(lsum[mt], pa[mt][ks], bone);   // row sums on tensor pipe
            #pragma unroll
            for (int dp = 0; dp < 4; dp++) {
                uint32_t bv[4];
                const int row = ks * 16 + vrow;
                const int c = (2 * dp + vch) ^ (vrow & 7);
                LDSM4T(bv[0], bv[1], bv[2], bv[3], vb + row * 128 + (c << 4));
                #pragma unroll
                for (int mt = 0; mt < 2; mt++) {
                    mma_f16(oacc[mt][2*dp],     pa[mt][ks], bv);
                    mma_f16(oacc[mt][2*dp + 1], pa[mt][ks], bv + 2);
                }
            }
        }
        __syncthreads();
    }

    const int g = lane >> 2, t = lane & 3;
    #pragma unroll
    for (int mt = 0; mt < 2; mt++) {
        const float inv0 = 1.0f / lsum[mt][0], inv1 = 1.0f / lsum[mt][2];
        const int r0 = q0 + wid * 32 + mt * 16 + g;
        #pragma unroll
        for (int n = 0; n < 8; n++) {
            const int col = h * 64 + n * 8 + 2 * t;
            *reinterpret_cast<__half2*>(O + (size_t)(r0 * BSZ + b) * ldo + col) =
                __floats2half2_rn(oacc[mt][n][0] * inv0, oacc[mt][n][1] * inv0);
            *reinterpret_cast<__half2*>(O + (size_t)((r0 + 8) * BSZ + b) * ldo + col) =
                __floats2half2_rn(oacc[mt][n][2] * inv1, oacc[mt][n][3] * inv1);
        }
    }
}

// ---------------- Fused residual-add + LayerNorm -------------------------------
__device__ __forceinline__ float block_sum_256(float v, float* red) {
    __syncthreads();
    #pragma unroll
    for (int off = 16; off > 0; off >>= 1) v += __shfl_down_sync(0xffffffffu, v, off);
    int lane = threadIdx.x & 31, w = threadIdx.x >> 5;
    if (lane == 0) red[w] = v;
    __syncthreads();
    if (w == 0) {
        v = (lane < 8) ? red[lane] : 0.0f;
        #pragma unroll
        for (int off = 4; off > 0; off >>= 1) v += __shfl_down_sync(0xffffffffu, v, off);
        if (lane == 0) red[0] = v;
    }
    __syncthreads();
    return red[0];
}

template <int WRITEH>
__global__ __launch_bounds__(256)
void add_ln_kernel(const float* __restrict__ x, const float* __restrict__ y,
                   const float* __restrict__ g, const float* __restrict__ beta,
                   float* __restrict__ out, __half* __restrict__ outh) {
    __shared__ float red[32];
    const int row = blockIdx.x;
    const int tid = threadIdx.x;
    const float* xr = x + (size_t)row * DMODEL;
    const float* yr = y + (size_t)row * DMODEL;

    float v[4];
    float sum = 0.0f;
    #pragma unroll
    for (int i = 0; i < 4; i++) {
        int c = tid + i * 256;
        v[i] = xr[c] + yr[c];
        sum += v[i];
    }
    float mean = block_sum_256(sum, red) * (1.0f / DMODEL);

    float vs = 0.0f;
    #pragma unroll
    for (int i = 0; i < 4; i++) { float d = v[i] - mean; vs += d * d; }
    float var = block_sum_256(vs, red) * (1.0f / DMODEL);
    float rstd = rsqrtf(var + 1e-5f);

    #pragma unroll
    for (int i = 0; i < 4; i++) {
        int c = tid + i * 256;
        float o = (v[i] - mean) * rstd * g[c] + beta[c];
        out[(size_t)row * DMODEL + c] = o;
        if (WRITEH) outh[(size_t)row * DMODEL + c] = __float2half_rn(o);
    }
}

// ---------------- fp32 -> fp16 convert kernels ----------------------------------
struct CvtJobs {
    const float4* src[7];
    __half2*      dst[7];
    int           off[8];   // cumulative n4 offsets, off[0] = 0
};

__global__ __launch_bounds__(256)
void megacvt_kernel(const __grid_constant__ CvtJobs j, int total) {
    int i = blockIdx.x * blockDim.x + threadIdx.x;
    if (i >= total) return;
    int k = 0;
    #pragma unroll
    for (int s = 1; s < 7; s++) if (i >= j.off[s]) k = s;
    int o = i - j.off[k];
    float4 v = j.src[k][o];
    j.dst[k][2*o]     = __floats2half2_rn(v.x, v.y);
    j.dst[k][2*o + 1] = __floats2half2_rn(v.z, v.w);
}

template <int M>
__global__ __launch_bounds__(256)
void cat_h_kernel(const float4* __restrict__ s0, const float4* __restrict__ s1,
                  const float4* __restrict__ s2, __half2* __restrict__ dst, int n4each,
                  const float* __restrict__ b0, const float* __restrict__ b1,
                  const float* __restrict__ b2, float* __restrict__ bdst, int nbeach) {
    int i = blockIdx.x * blockDim.x + threadIdx.x;
    int tot = M * n4each;
    if (i < tot) {
        int sel = i / n4each, off = i - sel * n4each;
        const float4* s = (sel == 0) ? s0 : ((sel == 1) ? s1 : s2);
        float4 v = s[off];
        dst[2*i]     = __floats2half2_rn(v.x, v.y);
        dst[2*i + 1] = __floats2half2_rn(v.z, v.w);
    } else {
        int j = i - tot;
        if (j < M * nbeach) {
            int sel = j / nbeach, off = j - sel * nbeach;
            const float* b = (sel == 0) ? b0 : ((sel == 1) ? b1 : b2);
            bdst[j] = b[off];
        }
    }
}

// ---------------- host orchestration -------------------------------------------
template <int RELU, int OUTH>
static void launch_gemm(const __half* A, const __half* W, const float* bias,
                        void* C, int M, int N, int K) {
    dim3 grid(N / 128, M / 128);
    gemm_h_kernel<RELU, OUTH><<<grid, 256, GEMM_DSMEM>>>(A, W, bias, C, N, K);
}

extern "C" void kernel_launch(void* const* d_in, const int* in_sizes, int n_in,
                              void* d_out, int out_size) {
    (void)in_sizes; (void)n_in; (void)out_size;

    const float* input = (const float*)d_in[0];
    const float* enc_  = (const float*)d_in[1];
    const float* sa_wq = (const float*)d_in[2];
    const float* sa_bq = (const float*)d_in[3];
    const float* sa_wk = (const float*)d_in[4];
    const float* sa_bk = (const float*)d_in[5];
    const float* sa_wv = (const float*)d_in[6];
    const float* sa_bv = (const float*)d_in[7];
    const float* sa_wo = (const float*)d_in[8];
    const float* sa_bo = (const float*)d_in[9];
    const float* ca_wq = (const float*)d_in[10];
    const float* ca_bq = (const float*)d_in[11];
    const float* ca_wk = (const float*)d_in[12];
    const float* ca_bk = (const float*)d_in[13];
    const float* ca_wv = (const float*)d_in[14];
    const float* ca_bv = (const float*)d_in[15];
    const float* ca_wo = (const float*)d_in[16];
    const float* ca_bo = (const float*)d_in[17];
    const float* w1    = (const float*)d_in[18];
    const float* b1    = (const float*)d_in[19];
    const float* w2    = (const float*)d_in[20];
    const float* b2    = (const float*)d_in[21];
    const float* ln1_g = (const float*)d_in[22];
    const float* ln1_b = (const float*)d_in[23];
    const float* ln2_g = (const float*)d_in[24];
    const float* ln2_b = (const float*)d_in[25];
    const float* ln3_g = (const float*)d_in[26];
    const float* ln3_b = (const float*)d_in[27];
    float* out = (float*)d_out;

    __half *qkvh, *qvh, *kh, *attnh, *ffnh, *rinh, *renh, *x1h, *x2h, *wh;
    float *tmp, *x1, *x2, *bias;
    cudaGetSymbolAddress((void**)&qkvh, g_qkvh);
    cudaGetSymbolAddress((void**)&qvh,  g_qvh);
    cudaGetSymbolAddress((void**)&kh,   g_kh);
    cudaGetSymbolAddress((void**)&attnh,g_attnh);
    cudaGetSymbolAddress((void**)&ffnh, g_ffnh);
    cudaGetSymbolAddress((void**)&rinh, g_rinh);
    cudaGetSymbolAddress((void**)&renh, g_renh);
    cudaGetSymbolAddress((void**)&x1h,  g_x1h);
    cudaGetSymbolAddress((void**)&x2h,  g_x2h);
    cudaGetSymbolAddress((void**)&wh,   g_wh);
    cudaGetSymbolAddress((void**)&tmp,  g_tmp);
    cudaGetSymbolAddress((void**)&x1,   g_x1);
    cudaGetSymbolAddress((void**)&x2,   g_x2);
    cudaGetSymbolAddress((void**)&bias, g_bias);

    cudaFuncSetAttribute(gemm_h_kernel<0,0>, cudaFuncAttributeMaxDynamicSharedMemorySize, GEMM_DSMEM);
    cudaFuncSetAttribute(gemm_h_kernel<0,1>, cudaFuncAttributeMaxDynamicSharedMemorySize, GEMM_DSMEM);
    cudaFuncSetAttribute(gemm_h_kernel<1,1>, cudaFuncAttributeMaxDynamicSharedMemorySize, GEMM_DSMEM);
    cudaFuncSetAttribute(attn_h_kernel, cudaFuncAttributeMaxDynamicSharedMemorySize, ATTN_DSMEM);

    const int MB = 1024 * 1024;
    __half* wh_sa_qkv = wh + 0*MB;
    __half* wh_sa_wo  = wh + 3*MB;
    __half* wh_ca_qv  = wh + 4*MB;
    __half* wh_ca_wk  = wh + 6*MB;
    __half* wh_ca_wo  = wh + 7*MB;
    __half* wh_w1     = wh + 8*MB;
    __half* wh_w2     = wh + 12*MB;
    float* b_sa_qkv = bias;
    float* b_ca_qv  = bias + 4096;

    const int n4w = MB / 4;
    dim3 agrid(SEQ / 128, BSZ * NHEAD);

    // ---- R9 schedule: all converts batched up front ----
    // #1: round+concat sa wq|wk|wv (+biases)
    {
        int tot = 3 * n4w + 3 * 1024;
        cat_h_kernel<3><<<(tot + 255) / 256, 256>>>(
            (const float4*)sa_wq, (const float4*)sa_wk, (const float4*)sa_wv,
            (__half2*)wh_sa_qkv, n4w, sa_bq, sa_bk, sa_bv, b_sa_qkv, 1024);
    }
    // #2: round+concat ca wq|wv (+biases)
    {
        int tot = 2 * n4w + 2 * 1024;
        cat_h_kernel<2><<<(tot + 255) / 256, 256>>>(
            (const float4*)ca_wq, (const float4*)ca_wv, nullptr,
            (__half2*)wh_ca_qv, n4w, ca_bq, ca_bv, nullptr, b_ca_qv, 1024);
    }
    // #3: one mega convert for everything else (incl. input/enc)
    {
        CvtJobs j;
        const float* srcs[7] = { input, enc_, sa_wo, ca_wk, ca_wo, w1, w2 };
        __half*      dsts[7] = { rinh, renh, wh_sa_wo, wh_ca_wk, wh_ca_wo, wh_w1, wh_w2 };
        const int    n4s [7] = { MB, MB, n4w, n4w, n4w, MB, MB };
        int cum = 0;
        for (int s = 0; s < 7; s++) {
            j.src[s] = (const float4*)srcs[s];
            j.dst[s] = (__half2*)dsts[s];
            j.off[s] = cum;
            cum += n4s[s];
        }
        j.off[7] = cum;
        megacvt_kernel<<<(cum + 255) / 256, 256>>>(j, cum);
    }

    // ---- self-attention ----
    launch_gemm<0,1>(rinh, wh_sa_qkv, b_sa_qkv, qkvh, MROWS, 3072, DMODEL);
    attn_h_kernel<<<agrid, 128, ATTN_DSMEM>>>(qkvh, 3072, qkvh + 1024, 3072,
                                              qkvh + 2048, 3072, attnh, 1024);
    launch_gemm<0,0>(attnh, wh_sa_wo, sa_bo, tmp, MROWS, DMODEL, DMODEL);
    add_ln_kernel<1><<<MROWS, 256>>>(input, tmp, ln1_g, ln1_b, x1, x1h);

    // ---- cross-attention: query=enc, key=x1, value=enc ----
    launch_gemm<0,1>(renh, wh_ca_qv, b_ca_qv, qvh, MROWS, 2048, DMODEL);
    launch_gemm<0,1>(x1h, wh_ca_wk, ca_bk, kh, MROWS, DMODEL, DMODEL);
    attn_h_kernel<<<agrid, 128, ATTN_DSMEM>>>(qvh, 2048, kh, 1024,
                                              qvh + 1024, 2048, attnh, 1024);
    launch_gemm<0,0>(attnh, wh_ca_wo, ca_bo, tmp, MROWS, DMODEL, DMODEL);
    add_ln_kernel<1><<<MROWS, 256>>>(x1, tmp, ln2_g, ln2_b, x2, x2h);

    // ---- FFN ----
    launch_gemm<1,1>(x2h, wh_w1, b1, ffnh, MROWS, DFF_, DMODEL);
    launch_gemm<0,0>(ffnh, wh_w2, b2, tmp, MROWS, DMODEL, DFF_);
    add_ln_kernel<0><<<MROWS, 256>>>(x2, tmp, ln3_g, ln3_b, out, nullptr);
}

// round 15
// speedup vs baseline: 1.0272x; 1.0208x over previous
#include <cuda_runtime.h>
#include <cuda.h>
#include <cuda_fp16.h>
#include <stdint.h>
#include <math.h>

#define SEQ    1024
#define BSZ    4
#define DMODEL 1024
#define NHEAD  16
#define HDIM   64
#define DFF_   4096
#define MROWS  (SEQ*BSZ)

// ---------------- scratch (device globals; no allocation allowed) ------------
__device__ __align__(1024) __half g_qkvh[MROWS*3072];
__device__ __align__(1024) __half g_qvh [MROWS*2048];
__device__ __align__(1024) __half g_kh  [MROWS*DMODEL];
__device__ __align__(1024) __half g_attnh[MROWS*DMODEL];
__device__ __align__(1024) __half g_ffnh[MROWS*DFF_];
__device__ __align__(1024) __half g_rinh[MROWS*DMODEL];
__device__ __align__(1024) __half g_renh[MROWS*DMODEL];
__device__ __align__(1024) __half g_x1h [MROWS*DMODEL];
__device__ __align__(1024) __half g_x2h [MROWS*DMODEL];
__device__ __align__(1024) __half g_wh  [16*1024*1024];
__device__ __align__(1024) float  g_tmp [MROWS*DMODEL];
__device__ __align__(1024) float  g_x1  [MROWS*DMODEL];
__device__ __align__(1024) float  g_x2  [MROWS*DMODEL];
__device__ __align__(1024) float  g_bias[8192];

// ---------------- helpers -------------------------------------------------
__device__ __forceinline__ uint32_t smem_u32(const void* p) {
    uint32_t a;
    asm("{ .reg .u64 t; cvta.to.shared.u64 t, %1; cvt.u32.u64 %0, t; }" : "=r"(a) : "l"(p));
    return a;
}
__device__ __forceinline__ void cp16(uint32_t dst, const void* src) {
    asm volatile("cp.async.cg.shared.global [%0], [%1], 16;" :: "r"(dst), "l"(src));
}
#define CP_COMMIT() asm volatile("cp.async.commit_group;" ::: "memory")
#define CP_WAIT(N)  asm volatile("cp.async.wait_group %0;" :: "n"(N) : "memory")

#define LDSM4(r0, r1, r2, r3, addr) \
    asm volatile("ldmatrix.sync.aligned.m8n8.x4.shared.b16 {%0,%1,%2,%3}, [%4];" \
        : "=r"(r0), "=r"(r1), "=r"(r2), "=r"(r3) : "r"(addr))
#define LDSM4T(r0, r1, r2, r3, addr) \
    asm volatile("ldmatrix.sync.aligned.m8n8.x4.trans.shared.b16 {%0,%1,%2,%3}, [%4];" \
        : "=r"(r0), "=r"(r1), "=r"(r2), "=r"(r3) : "r"(addr))

__device__ __forceinline__ void mma_f16(float c[4], const uint32_t a[4], const uint32_t b[2]) {
    asm volatile(
        "mma.sync.aligned.m16n8k16.row.col.f32.f16.f16.f32 "
        "{%0,%1,%2,%3}, {%4,%5,%6,%7}, {%8,%9}, {%0,%1,%2,%3};"
        : "+f"(c[0]), "+f"(c[1]), "+f"(c[2]), "+f"(c[3])
        : "r"(a[0]), "r"(a[1]), "r"(a[2]), "r"(a[3]), "r"(b[0]), "r"(b[1]));
}

// ---------------- fp16 mma GEMM: C[M,N] = A[M,K] @ W[N,K]^T + bias -----------
// CTA 128x128, 128 threads / 4 warps (2M x 2N of 64x64 warp tiles), BK=64,
// 3-stage cp.async, XOR-swizzled smem, 2 CTAs/SM. Halves redundant LDSM traffic
// vs 32x64 warp tiles (smem crossbar was the binding resource).
static constexpr int STAGE_B = 32768;                 // 16KB A + 16KB B
static constexpr int GEMM_DSMEM = 3 * STAGE_B;        // 98304

template <int RELU, int OUTH>
__global__ __launch_bounds__(128, 2)
void gemm_h_kernel(const __half* __restrict__ A, const __half* __restrict__ W,
                   const float* __restrict__ bias, void* __restrict__ Cv,
                   int Nn, int Kn) {
    extern __shared__ char dsmc[];
    const int tid = threadIdx.x, lane = tid & 31, wid = tid >> 5;
    const int g = lane >> 2, t = lane & 3;
    const int bm = blockIdx.y * 128, bn = blockIdx.x * 128;
    const int wm = (wid & 1) * 64, wn = (wid >> 1) * 64;

    float acc[4][8][4];
    #pragma unroll
    for (int mt = 0; mt < 4; mt++)
        #pragma unroll
        for (int nt = 0; nt < 8; nt++)
            #pragma unroll
            for (int i = 0; i < 4; i++) acc[mt][nt][i] = 0.0f;

    const int NIT = Kn / 64;
    const uint32_t sb = smem_u32(dsmc);

    const int lr = tid >> 3, lc = tid & 7;   // 16 rows x 8 chunks per pass
    auto load_stage = [&](int st, int kk) {
        uint32_t abase = sb + st * STAGE_B;
        uint32_t bbase = abase + 16384;
        #pragma unroll
        for (int p = 0; p < 8; p++) {
            int r = lr + p * 16;
            cp16(abase + r * 128 + ((lc ^ (r & 7)) << 4),
                 A + (size_t)(bm + r) * Kn + kk + lc * 8);
        }
        #pragma unroll
        for (int p = 0; p < 8; p++) {
            int r = lr + p * 16;
            cp16(bbase + r * 128 + ((lc ^ (r & 7)) << 4),
                 W + (size_t)(bn + r) * Kn + kk + lc * 8);
        }
        CP_COMMIT();
    };

    load_stage(0, 0);
    load_stage(1, 64);

    const int arow = wm + (lane & 15);
    const int axor = lane & 7;
    const int ach  = (lane >> 4) & 1;
    const int brow = wn + (lane & 7) + ((lane >> 4) & 1) * 8;
    const int bxor = lane & 7;
    const int bch  = (lane >> 3) & 1;

    for (int it = 0; it < NIT; it++) {
        const int cur = it % 3;
        CP_WAIT(1);
        __syncthreads();
        if (it + 2 < NIT) load_stage((it + 2) % 3, (it + 2) * 64);
        else              CP_COMMIT();

        const uint32_t ab = sb + cur * STAGE_B;
        const uint32_t bb = ab + 16384;

        #pragma unroll
        for (int ks = 0; ks < 4; ks++) {
            uint32_t a[4][4], b[8][2];
            const int cA = (2 * ks + ach) ^ axor;
            const int cB = (2 * ks + bch) ^ bxor;
            #pragma unroll
            for (int mt = 0; mt < 4; mt++)
                LDSM4(a[mt][0], a[mt][1], a[mt][2], a[mt][3],
                      ab + (arow + mt * 16) * 128 + (cA << 4));
            #pragma unroll
            for (int p = 0; p < 4; p++)
                LDSM4(b[2*p][0], b[2*p][1], b[2*p+1][0], b[2*p+1][1],
                      bb + (brow + p * 16) * 128 + (cB << 4));
            #pragma unroll
            for (int mt = 0; mt < 4; mt++)
                #pragma unroll
                for (int nt = 0; nt < 8; nt++)
                    mma_f16(acc[mt][nt], a[mt], b[nt]);
        }
    }

    // epilogue
    #pragma unroll
    for (int mt = 0; mt < 4; mt++) {
        const int r0 = bm + wm + mt * 16 + g;
        #pragma unroll
        for (int nt = 0; nt < 8; nt++) {
            const int col = bn + wn + nt * 8 + t * 2;
            const float b0 = bias[col], b1 = bias[col + 1];
            float v0 = acc[mt][nt][0] + b0, v1 = acc[mt][nt][1] + b1;
            float v2 = acc[mt][nt][2] + b0, v3 = acc[mt][nt][3] + b1;
            if (RELU) { v0 = fmaxf(v0, 0.f); v1 = fmaxf(v1, 0.f); v2 = fmaxf(v2, 0.f); v3 = fmaxf(v3, 0.f); }
            if (OUTH) {
                __half* C = (__half*)Cv;
                *reinterpret_cast<__half2*>(C + (size_t)r0 * Nn + col)       = __floats2half2_rn(v0, v1);
                *reinterpret_cast<__half2*>(C + (size_t)(r0 + 8) * Nn + col) = __floats2half2_rn(v2, v3);
            } else {
                float* C = (float*)Cv;
                *reinterpret_cast<float2*>(C + (size_t)r0 * Nn + col)       = make_float2(v0, v1);
                *reinterpret_cast<float2*>(C + (size_t)(r0 + 8) * Nn + col) = make_float2(v2, v3);
            }
        }
    }
}

// ---------------- fp16 tensor-core flash attention (register-P, R13) -----------
static constexpr int ATTN_DSMEM = 49152;

__global__ __launch_bounds__(128)
void attn_h_kernel(const __half* __restrict__ Q, int ldq,
                   const __half* __restrict__ K, int ldk,
                   const __half* __restrict__ V, int ldv,
                   __half* __restrict__ O, int ldo) {
    extern __shared__ char smc[];
    const uint32_t sQ = smem_u32(smc);               // Q staging: 16KB
    const uint32_t sK = sQ + 16384;                  // K: 2 bufs x 8192B
    const uint32_t sV = sQ + 32768;                  // V: 2 bufs x 8192B

    const int tid = threadIdx.x, lane = tid & 31, wid = tid >> 5;
    const int bh = blockIdx.y, b = bh & 3, h = bh >> 2;
    const int q0 = blockIdx.x * 128;

    #pragma unroll
    for (int i = 0; i < 8; i++) {
        int cl = tid + i * 128, r = cl >> 3, c = cl & 7;
        cp16(sQ + r * 128 + ((c ^ (r & 7)) << 4),
             Q + (size_t)((q0 + r) * BSZ + b) * ldq + h * 64 + c * 8);
    }
    CP_COMMIT();

    auto loadKV = [&](int kt_, int buf_) {
        #pragma unroll
        for (int i = 0; i < 4; i++) {
            int cl = tid + i * 128, r = cl >> 3, c = cl & 7;
            uint32_t off = buf_ * 8192 + r * 128 + ((c ^ (r & 7)) << 4);
            size_t srow = (size_t)((kt_ * 64 + r) * BSZ + b);
            cp16(sK + off, K + srow * ldk + h * 64 + c * 8);
            cp16(sV + off, V + srow * ldv + h * 64 + c * 8);
        }
        CP_COMMIT();
    };
    loadKV(0, 0);

    const int arow = wid * 32 + (lane & 15);
    const int axor = lane & 7;
    const int ach  = (lane >> 4) & 1;
    const int brow = (lane & 7) + ((lane >> 4) & 1) * 8;
    const int bxor = lane & 7;
    const int bch  = (lane >> 3) & 1;
    const int vrow = lane & 15;
    const int vch  = (lane >> 4) & 1;

    CP_WAIT(0);
    __syncthreads();

    uint32_t qa[2][4][4];
    {
        const __half2 sc = __float2half2_rn(0.125f);
        #pragma unroll
        for (int mt = 0; mt < 2; mt++)
            #pragma unroll
            for (int ks = 0; ks < 4; ks++) {
                const int c = (2 * ks + ach) ^ axor;
                LDSM4(qa[mt][ks][0], qa[mt][ks][1], qa[mt][ks][2], qa[mt][ks][3],
                      sQ + (arow + mt * 16) * 128 + (c << 4));
                #pragma unroll
                for (int i = 0; i < 4; i++) {
                    __half2 v = __hmul2(*reinterpret_cast<__half2*>(&qa[mt][ks][i]), sc);
                    qa[mt][ks][i] = *reinterpret_cast<uint32_t*>(&v);
                }
            }
    }

    float oacc[2][8][4];
    #pragma unroll
    for (int mt = 0; mt < 2; mt++)
        #pragma unroll
        for (int n = 0; n < 8; n++)
            #pragma unroll
            for (int i = 0; i < 4; i++) oacc[mt][n][i] = 0.0f;
    float lsum[2][4] = {{0.f,0.f,0.f,0.f},{0.f,0.f,0.f,0.f}};
    const uint32_t bone[2] = { 0x3C003C00u, 0x3C003C00u };

    for (int kt = 0; kt < 16; kt++) {
        const int buf = kt & 1;
        if (kt < 15) { loadKV(kt + 1, buf ^ 1); CP_WAIT(1); }
        else         { CP_WAIT(0); }
        __syncthreads();

        const uint32_t kb = sK + buf * 8192;
        const uint32_t vb = sV + buf * 8192;

        uint32_t pa[2][4][4];

        #pragma unroll
        for (int half = 0; half < 2; half++) {
            float sacc[2][4][4];
            #pragma unroll
            for (int mt = 0; mt < 2; mt++)
                #pragma unroll
                for (int n = 0; n < 4; n++)
                    #pragma unroll
                    for (int i = 0; i < 4; i++) sacc[mt][n][i] = 0.0f;

            #pragma unroll
            for (int ks = 0; ks < 4; ks++) {
                uint32_t bf[4][2];
                const int c = (2 * ks + bch) ^ bxor;
                #pragma unroll
                for (int p = 0; p < 2; p++) {
                    int row = half * 32 + p * 16 + brow;
                    LDSM4(bf[2*p][0], bf[2*p][1], bf[2*p+1][0], bf[2*p+1][1],
                          kb + row * 128 + (c << 4));
                }
                #pragma unroll
                for (int mt = 0; mt < 2; mt++)
                    #pragma unroll
                    for (int n = 0; n < 4; n++)
                        mma_f16(sacc[mt][n], qa[mt][ks], bf[n]);
            }
            #pragma unroll
            for (int mt = 0; mt < 2; mt++) {
                #pragma unroll
                for (int n = 0; n < 4; n++) {
                    half2 e01 = h2exp(__floats2half2_rn(sacc[mt][n][0], sacc[mt][n][1]));
                    half2 e23 = h2exp(__floats2half2_rn(sacc[mt][n][2], sacc[mt][n][3]));
                    const int j = 2 * half + (n >> 1);
                    const int r = (n & 1) * 2;
                    pa[mt][j][r]     = *reinterpret_cast<uint32_t*>(&e01);
                    pa[mt][j][r + 1] = *reinterpret_cast<uint32_t*>(&e23);
                }
            }
        }

        #pragma unroll
        for (int ks = 0; ks < 4; ks++) {
            #pragma unroll
            for (int mt = 0; mt < 2; mt++)
                mma_f16(lsum[mt], pa[mt][ks], bone);
            #pragma unroll
            for (int dp = 0; dp < 4; dp++) {
                uint32_t bv[4];
                const int row = ks * 16 + vrow;
                const int c = (2 * dp + vch) ^ (vrow & 7);
                LDSM4T(bv[0], bv[1], bv[2], bv[3], vb + row * 128 + (c << 4));
                #pragma unroll
                for (int mt = 0; mt < 2; mt++) {
                    mma_f16(oacc[mt][2*dp],     pa[mt][ks], bv);
                    mma_f16(oacc[mt][2*dp + 1], pa[mt][ks], bv + 2);
                }
            }
        }
        __syncthreads();
    }

    const int g = lane >> 2, t = lane & 3;
    #pragma unroll
    for (int mt = 0; mt < 2; mt++) {
        const float inv0 = 1.0f / lsum[mt][0], inv1 = 1.0f / lsum[mt][2];
        const int r0 = q0 + wid * 32 + mt * 16 + g;
        #pragma unroll
        for (int n = 0; n < 8; n++) {
            const int col = h * 64 + n * 8 + 2 * t;
            *reinterpret_cast<__half2*>(O + (size_t)(r0 * BSZ + b) * ldo + col) =
                __floats2half2_rn(oacc[mt][n][0] * inv0, oacc[mt][n][1] * inv0);
            *reinterpret_cast<__half2*>(O + (size_t)((r0 + 8) * BSZ + b) * ldo + col) =
                __floats2half2_rn(oacc[mt][n][2] * inv1, oacc[mt][n][3] * inv1);
        }
    }
}

// ---------------- Fused residual-add + LayerNorm -------------------------------
__device__ __forceinline__ float block_sum_256(float v, float* red) {
    __syncthreads();
    #pragma unroll
    for (int off = 16; off > 0; off >>= 1) v += __shfl_down_sync(0xffffffffu, v, off);
    int lane = threadIdx.x & 31, w = threadIdx.x >> 5;
    if (lane == 0) red[w] = v;
    __syncthreads();
    if (w == 0) {
        v = (lane < 8) ? red[lane] : 0.0f;
        #pragma unroll
        for (int off = 4; off > 0; off >>= 1) v += __shfl_down_sync(0xffffffffu, v, off);
        if (lane == 0) red[0] = v;
    }
    __syncthreads();
    return red[0];
}

template <int WRITEH>
__global__ __launch_bounds__(256)
void add_ln_kernel(const float* __restrict__ x, const float* __restrict__ y,
                   const float* __restrict__ g, const float* __restrict__ beta,
                   float* __restrict__ out, __half* __restrict__ outh) {
    __shared__ float red[32];
    const int row = blockIdx.x;
    const int tid = threadIdx.x;
    const float* xr = x + (size_t)row * DMODEL;
    const float* yr = y + (size_t)row * DMODEL;

    float v[4];
    float sum = 0.0f;
    #pragma unroll
    for (int i = 0; i < 4; i++) {
        int c = tid + i * 256;
        v[i] = xr[c] + yr[c];
        sum += v[i];
    }
    float mean = block_sum_256(sum, red) * (1.0f / DMODEL);

    float vs = 0.0f;
    #pragma unroll
    for (int i = 0; i < 4; i++) { float d = v[i] - mean; vs += d * d; }
    float var = block_sum_256(vs, red) * (1.0f / DMODEL);
    float rstd = rsqrtf(var + 1e-5f);

    #pragma unroll
    for (int i = 0; i < 4; i++) {
        int c = tid + i * 256;
        float o = (v[i] - mean) * rstd * g[c] + beta[c];
        out[(size_t)row * DMODEL + c] = o;
        if (WRITEH) outh[(size_t)row * DMODEL + c] = __float2half_rn(o);
    }
}

// ---------------- fp32 -> fp16 convert kernels ----------------------------------
struct CvtJobs {
    const float4* src[7];
    __half2*      dst[7];
    int           off[8];
};

__global__ __launch_bounds__(256)
void megacvt_kernel(const __grid_constant__ CvtJobs j, int total) {
    int i = blockIdx.x * blockDim.x + threadIdx.x;
    if (i >= total) return;
    int k = 0;
    #pragma unroll
    for (int s = 1; s < 7; s++) if (i >= j.off[s]) k = s;
    int o = i - j.off[k];
    float4 v = j.src[k][o];
    j.dst[k][2*o]     = __floats2half2_rn(v.x, v.y);
    j.dst[k][2*o + 1] = __floats2half2_rn(v.z, v.w);
}

template <int M>
__global__ __launch_bounds__(256)
void cat_h_kernel(const float4* __restrict__ s0, const float4* __restrict__ s1,
                  const float4* __restrict__ s2, __half2* __restrict__ dst, int n4each,
                  const float* __restrict__ b0, const float* __restrict__ b1,
                  const float* __restrict__ b2, float* __restrict__ bdst, int nbeach) {
    int i = blockIdx.x * blockDim.x + threadIdx.x;
    int tot = M * n4each;
    if (i < tot) {
        int sel = i / n4each, off = i - sel * n4each;
        const float4* s = (sel == 0) ? s0 : ((sel == 1) ? s1 : s2);
        float4 v = s[off];
        dst[2*i]     = __floats2half2_rn(v.x, v.y);
        dst[2*i + 1] = __floats2half2_rn(v.z, v.w);
    } else {
        int j = i - tot;
        if (j < M * nbeach) {
            int sel = j / nbeach, off = j - sel * nbeach;
            const float* b = (sel == 0) ? b0 : ((sel == 1) ? b1 : b2);
            bdst[j] = b[off];
        }
    }
}

// ---------------- host orchestration -------------------------------------------
template <int RELU, int OUTH>
static void launch_gemm(const __half* A, const __half* W, const float* bias,
                        void* C, int M, int N, int K) {
    dim3 grid(N / 128, M / 128);
    gemm_h_kernel<RELU, OUTH><<<grid, 128, GEMM_DSMEM>>>(A, W, bias, C, N, K);
}

extern "C" void kernel_launch(void* const* d_in, const int* in_sizes, int n_in,
                              void* d_out, int out_size) {
    (void)in_sizes; (void)n_in; (void)out_size;

    const float* input = (const float*)d_in[0];
    const float* enc_  = (const float*)d_in[1];
    const float* sa_wq = (const float*)d_in[2];
    const float* sa_bq = (const float*)d_in[3];
    const float* sa_wk = (const float*)d_in[4];
    const float* sa_bk = (const float*)d_in[5];
    const float* sa_wv = (const float*)d_in[6];
    const float* sa_bv = (const float*)d_in[7];
    const float* sa_wo = (const float*)d_in[8];
    const float* sa_bo = (const float*)d_in[9];
    const float* ca_wq = (const float*)d_in[10];
    const float* ca_bq = (const float*)d_in[11];
    const float* ca_wk = (const float*)d_in[12];
    const float* ca_bk = (const float*)d_in[13];
    const float* ca_wv = (const float*)d_in[14];
    const float* ca_bv = (const float*)d_in[15];
    const float* ca_wo = (const float*)d_in[16];
    const float* ca_bo = (const float*)d_in[17];
    const float* w1    = (const float*)d_in[18];
    const float* b1    = (const float*)d_in[19];
    const float* w2    = (const float*)d_in[20];
    const float* b2    = (const float*)d_in[21];
    const float* ln1_g = (const float*)d_in[22];
    const float* ln1_b = (const float*)d_in[23];
    const float* ln2_g = (const float*)d_in[24];
    const float* ln2_b = (const float*)d_in[25];
    const float* ln3_g = (const float*)d_in[26];
    const float* ln3_b = (const float*)d_in[27];
    float* out = (float*)d_out;

    __half *qkvh, *qvh, *kh, *attnh, *ffnh, *rinh, *renh, *x1h, *x2h, *wh;
    float *tmp, *x1, *x2, *bias;
    cudaGetSymbolAddress((void**)&qkvh, g_qkvh);
    cudaGetSymbolAddress((void**)&qvh,  g_qvh);
    cudaGetSymbolAddress((void**)&kh,   g_kh);
    cudaGetSymbolAddress((void**)&attnh,g_attnh);
    cudaGetSymbolAddress((void**)&ffnh, g_ffnh);
    cudaGetSymbolAddress((void**)&rinh, g_rinh);
    cudaGetSymbolAddress((void**)&renh, g_renh);
    cudaGetSymbolAddress((void**)&x1h,  g_x1h);
    cudaGetSymbolAddress((void**)&x2h,  g_x2h);
    cudaGetSymbolAddress((void**)&wh,   g_wh);
    cudaGetSymbolAddress((void**)&tmp,  g_tmp);
    cudaGetSymbolAddress((void**)&x1,   g_x1);
    cudaGetSymbolAddress((void**)&x2,   g_x2);
    cudaGetSymbolAddress((void**)&bias, g_bias);

    cudaFuncSetAttribute(gemm_h_kernel<0,0>, cudaFuncAttributeMaxDynamicSharedMemorySize, GEMM_DSMEM);
    cudaFuncSetAttribute(gemm_h_kernel<0,1>, cudaFuncAttributeMaxDynamicSharedMemorySize, GEMM_DSMEM);
    cudaFuncSetAttribute(gemm_h_kernel<1,1>, cudaFuncAttributeMaxDynamicSharedMemorySize, GEMM_DSMEM);
    cudaFuncSetAttribute(attn_h_kernel, cudaFuncAttributeMaxDynamicSharedMemorySize, ATTN_DSMEM);

    const int MB = 1024 * 1024;
    __half* wh_sa_qkv = wh + 0*MB;
    __half* wh_sa_wo  = wh + 3*MB;
    __half* wh_ca_qv  = wh + 4*MB;
    __half* wh_ca_wk  = wh + 6*MB;
    __half* wh_ca_wo  = wh + 7*MB;
    __half* wh_w1     = wh + 8*MB;
    __half* wh_w2     = wh + 12*MB;
    float* b_sa_qkv = bias;
    float* b_ca_qv  = bias + 4096;

    const int n4w = MB / 4;
    dim3 agrid(SEQ / 128, BSZ * NHEAD);

    // ---- converts batched up front ----
    {
        int tot = 3 * n4w + 3 * 1024;
        cat_h_kernel<3><<<(tot + 255) / 256, 256>>>(
            (const float4*)sa_wq, (const float4*)sa_wk, (const float4*)sa_wv,
            (__half2*)wh_sa_qkv, n4w, sa_bq, sa_bk, sa_bv, b_sa_qkv, 1024);
    }
    {
        int tot = 2 * n4w + 2 * 1024;
        cat_h_kernel<2><<<(tot + 255) / 256, 256>>>(
            (const float4*)ca_wq, (const float4*)ca_wv, nullptr,
            (__half2*)wh_ca_qv, n4w, ca_bq, ca_bv, nullptr, b_ca_qv, 1024);
    }
    {
        CvtJobs j;
        const float* srcs[7] = { input, enc_, sa_wo, ca_wk, ca_wo, w1, w2 };
        __half*      dsts[7] = { rinh, renh, wh_sa_wo, wh_ca_wk, wh_ca_wo, wh_w1, wh_w2 };
        const int    n4s [7] = { MB, MB, n4w, n4w, n4w, MB, MB };
        int cum = 0;
        for (int s = 0; s < 7; s++) {
            j.src[s] = (const float4*)srcs[s];
            j.dst[s] = (__half2*)dsts[s];
            j.off[s] = cum;
            cum += n4s[s];
        }
        j.off[7] = cum;
        megacvt_kernel<<<(cum + 255) / 256, 256>>>(j, cum);
    }

    // ---- self-attention ----
    launch_gemm<0,1>(rinh, wh_sa_qkv, b_sa_qkv, qkvh, MROWS, 3072, DMODEL);
    attn_h_kernel<<<agrid, 128, ATTN_DSMEM>>>(qkvh, 3072, qkvh + 1024, 3072,
                                              qkvh + 2048, 3072, attnh, 1024);
    launch_gemm<0,0>(attnh, wh_sa_wo, sa_bo, tmp, MROWS, DMODEL, DMODEL);
    add_ln_kernel<1><<<MROWS, 256>>>(input, tmp, ln1_g, ln1_b, x1, x1h);

    // ---- cross-attention: query=enc, key=x1, value=enc ----
    launch_gemm<0,1>(renh, wh_ca_qv, b_ca_qv, qvh, MROWS, 2048, DMODEL);
    launch_gemm<0,1>(x1h, wh_ca_wk, ca_bk, kh, MROWS, DMODEL, DMODEL);
    attn_h_kernel<<<agrid, 128, ATTN_DSMEM>>>(qvh, 2048, kh, 1024,
                                              qvh + 1024, 2048, attnh, 1024);
    launch_gemm<0,0>(attnh, wh_ca_wo, ca_bo, tmp, MROWS, DMODEL, DMODEL);
    add_ln_kernel<1><<<MROWS, 256>>>(x1, tmp, ln2_g, ln2_b, x2, x2h);

    // ---- FFN ----
    launch_gemm<1,1>(x2h, wh_w1, b1, ffnh, MROWS, DFF_, DMODEL);
    launch_gemm<0,0>(ffnh, wh_w2, b2, tmp, MROWS, DMODEL, DFF_);
    add_ln_kernel<0><<<MROWS, 256>>>(x2, tmp, ln3_g, ln3_b, out, nullptr);
}

// round 17
// speedup vs baseline: 1.0781x; 1.0496x over previous
#include <cuda_runtime.h>
#include <cuda.h>
#include <cuda_fp16.h>
#include <stdint.h>
#include <math.h>

#define SEQ    1024
#define BSZ    4
#define DMODEL 1024
#define NHEAD  16
#define HDIM   64
#define DFF_   4096
#define MROWS  (SEQ*BSZ)

// ---------------- scratch (device globals; no allocation allowed) ------------
__device__ __align__(1024) __half g_qkvh[MROWS*3072];
__device__ __align__(1024) __half g_qvh [MROWS*2048];
__device__ __align__(1024) __half g_kh  [MROWS*DMODEL];
__device__ __align__(1024) __half g_attnh[MROWS*DMODEL];
__device__ __align__(1024) __half g_ffnh[MROWS*DFF_];
__device__ __align__(1024) __half g_rinh[MROWS*DMODEL];
__device__ __align__(1024) __half g_renh[MROWS*DMODEL];
__device__ __align__(1024) __half g_x1h [MROWS*DMODEL];
__device__ __align__(1024) __half g_x2h [MROWS*DMODEL];
__device__ __align__(1024) __half g_wh  [16*1024*1024];
__device__ __align__(1024) float  g_tmp [MROWS*DMODEL];
__device__ __align__(1024) float  g_x1  [MROWS*DMODEL];
__device__ __align__(1024) float  g_x2  [MROWS*DMODEL];
__device__ __align__(1024) float  g_bias[8192];

// ---------------- helpers -------------------------------------------------
__device__ __forceinline__ uint32_t smem_u32(const void* p) {
    uint32_t a;
    asm("{ .reg .u64 t; cvta.to.shared.u64 t, %1; cvt.u32.u64 %0, t; }" : "=r"(a) : "l"(p));
    return a;
}
__device__ __forceinline__ void cp16(uint32_t dst, const void* src) {
    asm volatile("cp.async.cg.shared.global [%0], [%1], 16;" :: "r"(dst), "l"(src));
}
#define CP_COMMIT() asm volatile("cp.async.commit_group;" ::: "memory")
#define CP_WAIT(N)  asm volatile("cp.async.wait_group %0;" :: "n"(N) : "memory")

#define LDSM4(r0, r1, r2, r3, addr) \
    asm volatile("ldmatrix.sync.aligned.m8n8.x4.shared.b16 {%0,%1,%2,%3}, [%4];" \
        : "=r"(r0), "=r"(r1), "=r"(r2), "=r"(r3) : "r"(addr))
#define LDSM4T(r0, r1, r2, r3, addr) \
    asm volatile("ldmatrix.sync.aligned.m8n8.x4.trans.shared.b16 {%0,%1,%2,%3}, [%4];" \
        : "=r"(r0), "=r"(r1), "=r"(r2), "=r"(r3) : "r"(addr))

__device__ __forceinline__ void mma_f16(float c[4], const uint32_t a[4], const uint32_t b[2]) {
    asm volatile(
        "mma.sync.aligned.m16n8k16.row.col.f32.f16.f16.f32 "
        "{%0,%1,%2,%3}, {%4,%5,%6,%7}, {%8,%9}, {%0,%1,%2,%3};"
        : "+f"(c[0]), "+f"(c[1]), "+f"(c[2]), "+f"(c[3])
        : "r"(a[0]), "r"(a[1]), "r"(a[2]), "r"(a[3]), "r"(b[0]), "r"(b[1]));
}

// ---------------- fp16 mma GEMM (4 warps, 64x64 warp tiles, 2 CTAs/SM) ---------
static constexpr int STAGE_B = 32768;                 // 16KB A + 16KB B
static constexpr int GEMM_DSMEM = 3 * STAGE_B;        // 98304

template <int RELU, int OUTH>
__global__ __launch_bounds__(128, 2)
void gemm_h_kernel(const __half* __restrict__ A, const __half* __restrict__ W,
                   const float* __restrict__ bias, void* __restrict__ Cv,
                   int Nn, int Kn) {
    extern __shared__ char dsmc[];
    const int tid = threadIdx.x, lane = tid & 31, wid = tid >> 5;
    const int g = lane >> 2, t = lane & 3;
    const int bm = blockIdx.y * 128, bn = blockIdx.x * 128;
    const int wm = (wid & 1) * 64, wn = (wid >> 1) * 64;

    float acc[4][8][4];
    #pragma unroll
    for (int mt = 0; mt < 4; mt++)
        #pragma unroll
        for (int nt = 0; nt < 8; nt++)
            #pragma unroll
            for (int i = 0; i < 4; i++) acc[mt][nt][i] = 0.0f;

    const int NIT = Kn / 64;
    const uint32_t sb = smem_u32(dsmc);

    const int lr = tid >> 3, lc = tid & 7;
    auto load_stage = [&](int st, int kk) {
        uint32_t abase = sb + st * STAGE_B;
        uint32_t bbase = abase + 16384;
        #pragma unroll
        for (int p = 0; p < 8; p++) {
            int r = lr + p * 16;
            cp16(abase + r * 128 + ((lc ^ (r & 7)) << 4),
                 A + (size_t)(bm + r) * Kn + kk + lc * 8);
        }
        #pragma unroll
        for (int p = 0; p < 8; p++) {
            int r = lr + p * 16;
            cp16(bbase + r * 128 + ((lc ^ (r & 7)) << 4),
                 W + (size_t)(bn + r) * Kn + kk + lc * 8);
        }
        CP_COMMIT();
    };

    load_stage(0, 0);
    load_stage(1, 64);

    const int arow = wm + (lane & 15);
    const int axor = lane & 7;
    const int ach  = (lane >> 4) & 1;
    const int brow = wn + (lane & 7) + ((lane >> 4) & 1) * 8;
    const int bxor = lane & 7;
    const int bch  = (lane >> 3) & 1;

    for (int it = 0; it < NIT; it++) {
        const int cur = it % 3;
        CP_WAIT(1);
        __syncthreads();
        if (it + 2 < NIT) load_stage((it + 2) % 3, (it + 2) * 64);
        else              CP_COMMIT();

        const uint32_t ab = sb + cur * STAGE_B;
        const uint32_t bb = ab + 16384;

        #pragma unroll
        for (int ks = 0; ks < 4; ks++) {
            uint32_t a[4][4], b[8][2];
            const int cA = (2 * ks + ach) ^ axor;
            const int cB = (2 * ks + bch) ^ bxor;
            #pragma unroll
            for (int mt = 0; mt < 4; mt++)
                LDSM4(a[mt][0], a[mt][1], a[mt][2], a[mt][3],
                      ab + (arow + mt * 16) * 128 + (cA << 4));
            #pragma unroll
            for (int p = 0; p < 4; p++)
                LDSM4(b[2*p][0], b[2*p][1], b[2*p+1][0], b[2*p+1][1],
                      bb + (brow + p * 16) * 128 + (cB << 4));
            #pragma unroll
            for (int mt = 0; mt < 4; mt++)
                #pragma unroll
                for (int nt = 0; nt < 8; nt++)
                    mma_f16(acc[mt][nt], a[mt], b[nt]);
        }
    }

    // epilogue
    #pragma unroll
    for (int mt = 0; mt < 4; mt++) {
        const int r0 = bm + wm + mt * 16 + g;
        #pragma unroll
        for (int nt = 0; nt < 8; nt++) {
            const int col = bn + wn + nt * 8 + t * 2;
            const float b0 = bias[col], b1 = bias[col + 1];
            float v0 = acc[mt][nt][0] + b0, v1 = acc[mt][nt][1] + b1;
            float v2 = acc[mt][nt][2] + b0, v3 = acc[mt][nt][3] + b1;
            if (RELU) { v0 = fmaxf(v0, 0.f); v1 = fmaxf(v1, 0.f); v2 = fmaxf(v2, 0.f); v3 = fmaxf(v3, 0.f); }
            if (OUTH) {
                __half* C = (__half*)Cv;
                *reinterpret_cast<__half2*>(C + (size_t)r0 * Nn + col)       = __floats2half2_rn(v0, v1);
                *reinterpret_cast<__half2*>(C + (size_t)(r0 + 8) * Nn + col) = __floats2half2_rn(v2, v3);
            } else {
                float* C = (float*)Cv;
                *reinterpret_cast<float2*>(C + (size_t)r0 * Nn + col)       = make_float2(v0, v1);
                *reinterpret_cast<float2*>(C + (size_t)(r0 + 8) * Nn + col) = make_float2(v2, v3);
            }
        }
    }
}

// ---------------- fp16 tensor-core flash attention (register-P, 3-buffer KV) ---
static constexpr int ATTN_DSMEM = 16384 + 3*8192*2;   // Q 16KB + K 24KB + V 24KB

__global__ __launch_bounds__(128)
void attn_h_kernel(const __half* __restrict__ Q, int ldq,
                   const __half* __restrict__ K, int ldk,
                   const __half* __restrict__ V, int ldv,
                   __half* __restrict__ O, int ldo) {
    extern __shared__ char smc[];
    const uint32_t sQ = smem_u32(smc);               // Q staging: 16KB
    const uint32_t sK = sQ + 16384;                  // K: 3 bufs x 8192B
    const uint32_t sV = sK + 24576;                  // V: 3 bufs x 8192B

    const int tid = threadIdx.x, lane = tid & 31, wid = tid >> 5;
    const int bh = blockIdx.y, b = bh & 3, h = bh >> 2;
    const int q0 = blockIdx.x * 128;

    #pragma unroll
    for (int i = 0; i < 8; i++) {
        int cl = tid + i * 128, r = cl >> 3, c = cl & 7;
        cp16(sQ + r * 128 + ((c ^ (r & 7)) << 4),
             Q + (size_t)((q0 + r) * BSZ + b) * ldq + h * 64 + c * 8);
    }
    CP_COMMIT();

    auto loadKV = [&](int kt_, int buf_) {
        #pragma unroll
        for (int i = 0; i < 4; i++) {
            int cl = tid + i * 128, r = cl >> 3, c = cl & 7;
            uint32_t off = buf_ * 8192 + r * 128 + ((c ^ (r & 7)) << 4);
            size_t srow = (size_t)((kt_ * 64 + r) * BSZ + b);
            cp16(sK + off, K + srow * ldk + h * 64 + c * 8);
            cp16(sV + off, V + srow * ldv + h * 64 + c * 8);
        }
        CP_COMMIT();
    };

    const int arow = wid * 32 + (lane & 15);
    const int axor = lane & 7;
    const int ach  = (lane >> 4) & 1;
    const int brow = (lane & 7) + ((lane >> 4) & 1) * 8;
    const int bxor = lane & 7;
    const int bch  = (lane >> 3) & 1;
    const int vrow = lane & 15;
    const int vch  = (lane >> 4) & 1;

    CP_WAIT(0);     // Q ready
    __syncthreads();

    uint32_t qa[2][4][4];
    {
        const __half2 sc = __float2half2_rn(0.125f);
        #pragma unroll
        for (int mt = 0; mt < 2; mt++)
            #pragma unroll
            for (int ks = 0; ks < 4; ks++) {
                const int c = (2 * ks + ach) ^ axor;
                LDSM4(qa[mt][ks][0], qa[mt][ks][1], qa[mt][ks][2], qa[mt][ks][3],
                      sQ + (arow + mt * 16) * 128 + (c << 4));
                #pragma unroll
                for (int i = 0; i < 4; i++) {
                    __half2 v = __hmul2(*reinterpret_cast<__half2*>(&qa[mt][ks][i]), sc);
                    qa[mt][ks][i] = *reinterpret_cast<uint32_t*>(&v);
                }
            }
    }

    loadKV(0, 0);
    loadKV(1, 1);

    float oacc[2][8][4];
    #pragma unroll
    for (int mt = 0; mt < 2; mt++)
        #pragma unroll
        for (int n = 0; n < 8; n++)
            #pragma unroll
            for (int i = 0; i < 4; i++) oacc[mt][n][i] = 0.0f;
    float lsum[2][4] = {{0.f,0.f,0.f,0.f},{0.f,0.f,0.f,0.f}};
    const uint32_t bone[2] = { 0x3C003C00u, 0x3C003C00u };

    for (int kt = 0; kt < 16; kt++) {
        const int buf = kt % 3;
        CP_WAIT(1);
        __syncthreads();
        if (kt + 2 < 16) loadKV(kt + 2, (kt + 2) % 3);
        else             CP_COMMIT();

        const uint32_t kb = sK + buf * 8192;
        const uint32_t vb = sV + buf * 8192;

        uint32_t pa[2][4][4];

        #pragma unroll
        for (int half = 0; half < 2; half++) {
            float sacc[2][4][4];
            #pragma unroll
            for (int mt = 0; mt < 2; mt++)
                #pragma unroll
                for (int n = 0; n < 4; n++)
                    #pragma unroll
                    for (int i = 0; i < 4; i++) sacc[mt][n][i] = 0.0f;

            #pragma unroll
            for (int ks = 0; ks < 4; ks++) {
                uint32_t bf[4][2];
                const int c = (2 * ks + bch) ^ bxor;
                #pragma unroll
                for (int p = 0; p < 2; p++) {
                    int row = half * 32 + p * 16 + brow;
                    LDSM4(bf[2*p][0], bf[2*p][1], bf[2*p+1][0], bf[2*p+1][1],
                          kb + row * 128 + (c << 4));
                }
                #pragma unroll
                for (int mt = 0; mt < 2; mt++)
                    #pragma unroll
                    for (int n = 0; n < 4; n++)
                        mma_f16(sacc[mt][n], qa[mt][ks], bf[n]);
            }
            #pragma unroll
            for (int mt = 0; mt < 2; mt++) {
                #pragma unroll
                for (int n = 0; n < 4; n++) {
                    half2 e01 = h2exp(__floats2half2_rn(sacc[mt][n][0], sacc[mt][n][1]));
                    half2 e23 = h2exp(__floats2half2_rn(sacc[mt][n][2], sacc[mt][n][3]));
                    const int j = 2 * half + (n >> 1);
                    const int r = (n & 1) * 2;
                    pa[mt][j][r]     = *reinterpret_cast<uint32_t*>(&e01);
                    pa[mt][j][r + 1] = *reinterpret_cast<uint32_t*>(&e23);
                }
            }
        }

        #pragma unroll
        for (int ks = 0; ks < 4; ks++) {
            #pragma unroll
            for (int mt = 0; mt < 2; mt++)
                mma_f16(lsum[mt], pa[mt][ks], bone);
            #pragma unroll
            for (int dp = 0; dp < 4; dp++) {
                uint32_t bv[4];
                const int row = ks * 16 + vrow;
                const int c = (2 * dp + vch) ^ (vrow & 7);
                LDSM4T(bv[0], bv[1], bv[2], bv[3], vb + row * 128 + (c << 4));
                #pragma unroll
                for (int mt = 0; mt < 2; mt++) {
                    mma_f16(oacc[mt][2*dp],     pa[mt][ks], bv);
                    mma_f16(oacc[mt][2*dp + 1], pa[mt][ks], bv + 2);
                }
            }
        }
        // no bottom sync: 3-buffer ring + top barrier keep reuse safe
    }

    const int g = lane >> 2, t = lane & 3;
    #pragma unroll
    for (int mt = 0; mt < 2; mt++) {
        const float inv0 = 1.0f / lsum[mt][0], inv1 = 1.0f / lsum[mt][2];
        const int r0 = q0 + wid * 32 + mt * 16 + g;
        #pragma unroll
        for (int n = 0; n < 8; n++) {
            const int col = h * 64 + n * 8 + 2 * t;
            *reinterpret_cast<__half2*>(O + (size_t)(r0 * BSZ + b) * ldo + col) =
                __floats2half2_rn(oacc[mt][n][0] * inv0, oacc[mt][n][1] * inv0);
            *reinterpret_cast<__half2*>(O + (size_t)((r0 + 8) * BSZ + b) * ldo + col) =
                __floats2half2_rn(oacc[mt][n][2] * inv1, oacc[mt][n][3] * inv1);
        }
    }
}

// ---------------- Fused residual-add + LayerNorm -------------------------------
__device__ __forceinline__ float block_sum_256(float v, float* red) {
    __syncthreads();
    #pragma unroll
    for (int off = 16; off > 0; off >>= 1) v += __shfl_down_sync(0xffffffffu, v, off);
    int lane = threadIdx.x & 31, w = threadIdx.x >> 5;
    if (lane == 0) red[w] = v;
    __syncthreads();
    if (w == 0) {
        v = (lane < 8) ? red[lane] : 0.0f;
        #pragma unroll
        for (int off = 4; off > 0; off >>= 1) v += __shfl_down_sync(0xffffffffu, v, off);
        if (lane == 0) red[0] = v;
    }
    __syncthreads();
    return red[0];
}

template <int WRITEH>
__global__ __launch_bounds__(256)
void add_ln_kernel(const float* __restrict__ x, const float* __restrict__ y,
                   const float* __restrict__ g, const float* __restrict__ beta,
                   float* __restrict__ out, __half* __restrict__ outh) {
    __shared__ float red[32];
    const int row = blockIdx.x;
    const int tid = threadIdx.x;
    const float* xr = x + (size_t)row * DMODEL;
    const float* yr = y + (size_t)row * DMODEL;

    float v[4];
    float sum = 0.0f;
    #pragma unroll
    for (int i = 0; i < 4; i++) {
        int c = tid + i * 256;
        v[i] = xr[c] + yr[c];
        sum += v[i];
    }
    float mean = block_sum_256(sum, red) * (1.0f / DMODEL);

    float vs = 0.0f;
    #pragma unroll
    for (int i = 0; i < 4; i++) { float d = v[i] - mean; vs += d * d; }
    float var = block_sum_256(vs, red) * (1.0f / DMODEL);
    float rstd = rsqrtf(var + 1e-5f);

    #pragma unroll
    for (int i = 0; i < 4; i++) {
        int c = tid + i * 256;
        float o = (v[i] - mean) * rstd * g[c] + beta[c];
        out[(size_t)row * DMODEL + c] = o;
        if (WRITEH) outh[(size_t)row * DMODEL + c] = __float2half_rn(o);
    }
}

// ---------------- single prep kernel: 12 cvt segments + 5 bias copies ----------
struct PrepJobs {
    const float4* src[12];
    __half2*      dst[12];
    int           off[13];     // cumulative float4 offsets
    const float*  bsrc[5];
    int           bdst[5];     // offsets into g_bias
};

__global__ __launch_bounds__(256)
void prep_kernel(const __grid_constant__ PrepJobs j, int total4, float* __restrict__ bias) {
    int i = blockIdx.x * blockDim.x + threadIdx.x;
    if (i < total4) {
        int k = 0;
        #pragma unroll
        for (int s = 1; s < 12; s++) if (i >= j.off[s]) k = s;
        int o = i - j.off[k];
        float4 v = j.src[k][o];
        j.dst[k][2*o]     = __floats2half2_rn(v.x, v.y);
        j.dst[k][2*o + 1] = __floats2half2_rn(v.z, v.w);
    } else {
        int idx = i - total4;
        if (idx < 5 * 1024) {
            int s = idx >> 10, o = idx & 1023;
            bias[j.bdst[s] + o] = j.bsrc[s][o];
        }
    }
}

// ---------------- host orchestration -------------------------------------------
template <int RELU, int OUTH>
static void launch_gemm(const __half* A, const __half* W, const float* bias,
                        void* C, int M, int N, int K, cudaStream_t st = 0) {
    dim3 grid(N / 128, M / 128);
    gemm_h_kernel<RELU, OUTH><<<grid, 128, GEMM_DSMEM, st>>>(A, W, bias, C, N, K);
}

extern "C" void kernel_launch(void* const* d_in, const int* in_sizes, int n_in,
                              void* d_out, int out_size) {
    (void)in_sizes; (void)n_in; (void)out_size;

    const float* input = (const float*)d_in[0];
    const float* enc_  = (const float*)d_in[1];
    const float* sa_wq = (const float*)d_in[2];
    const float* sa_bq = (const float*)d_in[3];
    const float* sa_wk = (const float*)d_in[4];
    const float* sa_bk = (const float*)d_in[5];
    const float* sa_wv = (const float*)d_in[6];
    const float* sa_bv = (const float*)d_in[7];
    const float* sa_wo = (const float*)d_in[8];
    const float* sa_bo = (const float*)d_in[9];
    const float* ca_wq = (const float*)d_in[10];
    const float* ca_bq = (const float*)d_in[11];
    const float* ca_wk = (const float*)d_in[12];
    const float* ca_bk = (const float*)d_in[13];
    const float* ca_wv = (const float*)d_in[14];
    const float* ca_bv = (const float*)d_in[15];
    const float* ca_wo = (const float*)d_in[16];
    const float* ca_bo = (const float*)d_in[17];
    const float* w1    = (const float*)d_in[18];
    const float* b1    = (const float*)d_in[19];
    const float* w2    = (const float*)d_in[20];
    const float* b2    = (const float*)d_in[21];
    const float* ln1_g = (const float*)d_in[22];
    const float* ln1_b = (const float*)d_in[23];
    const float* ln2_g = (const float*)d_in[24];
    const float* ln2_b = (const float*)d_in[25];
    const float* ln3_g = (const float*)d_in[26];
    const float* ln3_b = (const float*)d_in[27];
    float* out = (float*)d_out;

    __half *qkvh, *qvh, *kh, *attnh, *ffnh, *rinh, *renh, *x1h, *x2h, *wh;
    float *tmp, *x1, *x2, *bias;
    cudaGetSymbolAddress((void**)&qkvh, g_qkvh);
    cudaGetSymbolAddress((void**)&qvh,  g_qvh);
    cudaGetSymbolAddress((void**)&kh,   g_kh);
    cudaGetSymbolAddress((void**)&attnh,g_attnh);
    cudaGetSymbolAddress((void**)&ffnh, g_ffnh);
    cudaGetSymbolAddress((void**)&rinh, g_rinh);
    cudaGetSymbolAddress((void**)&renh, g_renh);
    cudaGetSymbolAddress((void**)&x1h,  g_x1h);
    cudaGetSymbolAddress((void**)&x2h,  g_x2h);
    cudaGetSymbolAddress((void**)&wh,   g_wh);
    cudaGetSymbolAddress((void**)&tmp,  g_tmp);
    cudaGetSymbolAddress((void**)&x1,   g_x1);
    cudaGetSymbolAddress((void**)&x2,   g_x2);
    cudaGetSymbolAddress((void**)&bias, g_bias);

    cudaFuncSetAttribute(gemm_h_kernel<0,0>, cudaFuncAttributeMaxDynamicSharedMemorySize, GEMM_DSMEM);
    cudaFuncSetAttribute(gemm_h_kernel<0,1>, cudaFuncAttributeMaxDynamicSharedMemorySize, GEMM_DSMEM);
    cudaFuncSetAttribute(gemm_h_kernel<1,1>, cudaFuncAttributeMaxDynamicSharedMemorySize, GEMM_DSMEM);
    cudaFuncSetAttribute(attn_h_kernel, cudaFuncAttributeMaxDynamicSharedMemorySize, ATTN_DSMEM);

    const int MB = 1024 * 1024;
    __half* wh_sa_qkv = wh + 0*MB;
    __half* wh_sa_wo  = wh + 3*MB;
    __half* wh_ca_qv  = wh + 4*MB;
    __half* wh_ca_wk  = wh + 6*MB;
    __half* wh_ca_wo  = wh + 7*MB;
    __half* wh_w1     = wh + 8*MB;
    __half* wh_w2     = wh + 12*MB;
    float* b_sa_qkv = bias;          // [3072]
    float* b_ca_qv  = bias + 4096;   // [2048]

    dim3 agrid(SEQ / 128, BSZ * NHEAD);

    cudaStream_t aux;
    cudaStreamCreateWithFlags(&aux, cudaStreamNonBlocking);
    cudaEvent_t evP, evQV;
    cudaEventCreateWithFlags(&evP,  cudaEventDisableTiming);
    cudaEventCreateWithFlags(&evQV, cudaEventDisableTiming);

    // ---- one prep kernel: all weight/activation converts + bias concat ----
    {
        PrepJobs j;
        const float* srcs[12] = { sa_wq, sa_wk, sa_wv, ca_wq, ca_wv,
                                  input, enc_, sa_wo, ca_wk, ca_wo, w1, w2 };
        __half* dsts[12] = { wh_sa_qkv, wh_sa_qkv + MB, wh_sa_qkv + 2*MB,
                             wh_ca_qv,  wh_ca_qv + MB,
                             rinh, renh, wh_sa_wo, wh_ca_wk, wh_ca_wo, wh_w1, wh_w2 };
        // sizes in float4: weights 1024x1024 = MB/4; activations 4096x1024 = MB;
        // w1/w2 4096x1024(x4) = MB.   (R16 bug: input/enc were MB/4 — fixed)
        const int n4s[12] = { MB/4, MB/4, MB/4, MB/4, MB/4,
                              MB, MB, MB/4, MB/4, MB/4, MB, MB };
        int cum = 0;
        for (int s = 0; s < 12; s++) {
            j.src[s] = (const float4*)srcs[s];
            j.dst[s] = (__half2*)dsts[s];
            j.off[s] = cum;
            cum += n4s[s];
        }
        j.off[12] = cum;
        const float* bsrcs[5] = { sa_bq, sa_bk, sa_bv, ca_bq, ca_bv };
        const int    bdsts[5] = { 0, 1024, 2048, 4096, 5120 };
        for (int s = 0; s < 5; s++) { j.bsrc[s] = bsrcs[s]; j.bdst[s] = bdsts[s]; }
        int total = cum + 5 * 1024;
        prep_kernel<<<(total + 255) / 256, 256>>>(j, cum, bias);
    }
    cudaEventRecord(evP, 0);

    // ---- aux stream: ca_qv GEMM overlaps the entire self-attention block ----
    cudaStreamWaitEvent(aux, evP, 0);
    launch_gemm<0,1>(renh, wh_ca_qv, b_ca_qv, qvh, MROWS, 2048, DMODEL, aux);
    cudaEventRecord(evQV, aux);

    // ---- self-attention (main stream) ----
    launch_gemm<0,1>(rinh, wh_sa_qkv, b_sa_qkv, qkvh, MROWS, 3072, DMODEL);
    attn_h_kernel<<<agrid, 128, ATTN_DSMEM>>>(qkvh, 3072, qkvh + 1024, 3072,
                                              qkvh + 2048, 3072, attnh, 1024);
    launch_gemm<0,0>(attnh, wh_sa_wo, sa_bo, tmp, MROWS, DMODEL, DMODEL);
    add_ln_kernel<1><<<MROWS, 256>>>(input, tmp, ln1_g, ln1_b, x1, x1h);

    // ---- cross-attention: query=enc, key=x1, value=enc ----
    launch_gemm<0,1>(x1h, wh_ca_wk, ca_bk, kh, MROWS, DMODEL, DMODEL);
    cudaStreamWaitEvent(0, evQV, 0);    // join: attn2 needs qvh
    attn_h_kernel<<<agrid, 128, ATTN_DSMEM>>>(qvh, 2048, kh, 1024,
                                              qvh + 1024, 2048, attnh, 1024);
    launch_gemm<0,0>(attnh, wh_ca_wo, ca_bo, tmp, MROWS, DMODEL, DMODEL);
    add_ln_kernel<1><<<MROWS, 256>>>(x1, tmp, ln2_g, ln2_b, x2, x2h);

    // ---- FFN ----
    launch_gemm<1,1>(x2h, wh_w1, b1, ffnh, MROWS, DFF_, DMODEL);
    launch_gemm<0,0>(ffnh, wh_w2, b2, tmp, MROWS, DMODEL, DFF_);
    add_ln_kernel<0><<<MROWS, 256>>>(x2, tmp, ln3_g, ln3_b, out, nullptr);
}